// round 8
// baseline (speedup 1.0000x reference)
#include <cuda_runtime.h>
#include <cstddef>

// Problem constants (B=2, S=2048, H=2048, N=16 heads, HN=128)
#define S_LEN 2048
#define H_DIM 2048
#define NHEAD 16
#define HDIM  128
static __device__ __constant__ float kRSqrtHD = 0.08838834764831845f; // 1/sqrt(128)

// Scratch (device globals — allowed; no runtime allocation)
__device__ float g_qT [32u * 128u * 2048u];   // [b*16+n][d][s]   32 MB
__device__ float g_kT [32u * 128u * 2048u];   // [b*16+n][d][s]   32 MB
__device__ float g_v  [32u * 2048u * 128u];   // [b*16+n][s][d]   32 MB
__device__ float g_ctx[2u * 2048u * 2048u];   // [b][s][h]        32 MB

// ---------------------------------------------------------------------------
// SGEMM: C[M,2048-reduction] = A[M,2048] @ W[Ncols,2048]^T + bias
// 128x128 block, Ktile=8, 256 threads, 8x8 microtile, register prefetch.
// MODE 0: QKV epilogue (scatter into g_qT/g_kT/g_v, scale q by 1/sqrt(HD))
// MODE 1: dense epilogue (A is g_ctx; plain row-major store to Out)
// ---------------------------------------------------------------------------
template <int MODE>
__global__ void __launch_bounds__(256) sgemm_nt(
    const float* __restrict__ A,
    const float* __restrict__ W,
    const float* __restrict__ bias,
    float* __restrict__ Out)
{
    constexpr int K = 2048;
    __shared__ float As[8][128];
    __shared__ float Ws[8][128];

    const int tid = threadIdx.x;
    const int tx = tid & 15;
    const int ty = tid >> 4;
    const int rowBase = blockIdx.y * 128;
    const int colBase = blockIdx.x * 128;

    const float* Aeff = (MODE == 1) ? (const float*)g_ctx : A;

    const int lr = tid >> 1;          // 0..127
    const int lc = (tid & 1) * 4;     // 0 or 4
    const float* Ap = Aeff + (size_t)(rowBase + lr) * K + lc;
    const float* Wp = W    + (size_t)(colBase + lr) * K + lc;

    float acc[8][8];
#pragma unroll
    for (int i = 0; i < 8; i++)
#pragma unroll
        for (int j = 0; j < 8; j++) acc[i][j] = 0.0f;

    float4 pa = *(const float4*)Ap;
    float4 pw = *(const float4*)Wp;

    const int nkt = K / 8;
    for (int kt = 0; kt < nkt; kt++) {
        As[lc + 0][lr] = pa.x; As[lc + 1][lr] = pa.y;
        As[lc + 2][lr] = pa.z; As[lc + 3][lr] = pa.w;
        Ws[lc + 0][lr] = pw.x; Ws[lc + 1][lr] = pw.y;
        Ws[lc + 2][lr] = pw.z; Ws[lc + 3][lr] = pw.w;
        __syncthreads();

        if (kt + 1 < nkt) {
            pa = *(const float4*)(Ap + (size_t)(kt + 1) * 8);
            pw = *(const float4*)(Wp + (size_t)(kt + 1) * 8);
        }

#pragma unroll
        for (int k = 0; k < 8; k++) {
            float4 a0 = *(const float4*)&As[k][ty * 4];
            float4 a1 = *(const float4*)&As[k][64 + ty * 4];
            float4 w0 = *(const float4*)&Ws[k][tx * 4];
            float4 w1 = *(const float4*)&Ws[k][64 + tx * 4];
            float am[8] = {a0.x, a0.y, a0.z, a0.w, a1.x, a1.y, a1.z, a1.w};
            float wn[8] = {w0.x, w0.y, w0.z, w0.w, w1.x, w1.y, w1.z, w1.w};
#pragma unroll
            for (int i = 0; i < 8; i++)
#pragma unroll
                for (int j = 0; j < 8; j++)
                    acc[i][j] += am[i] * wn[j];
        }
        __syncthreads();
    }

    int cidx[8], ridx[8];
#pragma unroll
    for (int j = 0; j < 8; j++) cidx[j] = (j < 4) ? (tx * 4 + j) : (64 + tx * 4 + (j - 4));
#pragma unroll
    for (int i = 0; i < 8; i++) ridx[i] = (i < 4) ? (ty * 4 + i) : (64 + ty * 4 + (i - 4));

    // bias add
#pragma unroll
    for (int j = 0; j < 8; j++) {
        float bv = bias[colBase + cidx[j]];
#pragma unroll
        for (int i = 0; i < 8; i++) acc[i][j] += bv;
    }

    if (MODE == 0) {
        const int part = colBase >> 11;           // 0=q 1=k 2=v
        const int head = (colBase & 2047) >> 7;   // column block lies within one head
        const int b    = rowBase >> 11;
        const int s0   = rowBase & 2047;

        if (part < 2) {
            float* dst = (part == 0) ? g_qT : g_kT;
            const float scale = (part == 0) ? kRSqrtHD : 1.0f;
            float* base = dst + ((size_t)(b * NHEAD + head) * HDIM) * (size_t)S_LEN;
#pragma unroll
            for (int j = 0; j < 8; j++) {
                float* col = base + (size_t)cidx[j] * S_LEN + s0;
#pragma unroll
                for (int g = 0; g < 2; g++) {
                    int r0 = g * 64 + ty * 4;
                    float4 vv;
                    vv.x = acc[g * 4 + 0][j] * scale;
                    vv.y = acc[g * 4 + 1][j] * scale;
                    vv.z = acc[g * 4 + 2][j] * scale;
                    vv.w = acc[g * 4 + 3][j] * scale;
                    *(float4*)&col[r0] = vv;
                }
            }
        } else {
            float* base = g_v + ((size_t)(b * NHEAD + head) * S_LEN) * HDIM;
#pragma unroll
            for (int i = 0; i < 8; i++) {
                float* row = base + (size_t)(s0 + ridx[i]) * HDIM;
#pragma unroll
                for (int g = 0; g < 2; g++) {
                    int c0 = g * 64 + tx * 4;
                    float4 vv;
                    vv.x = acc[i][g * 4 + 0];
                    vv.y = acc[i][g * 4 + 1];
                    vv.z = acc[i][g * 4 + 2];
                    vv.w = acc[i][g * 4 + 3];
                    *(float4*)&row[c0] = vv;
                }
            }
        }
    } else {
#pragma unroll
        for (int i = 0; i < 8; i++) {
            int row = rowBase + ridx[i];
#pragma unroll
            for (int g = 0; g < 2; g++) {
                int c0 = colBase + g * 64 + tx * 4;
                float4 vv;
                vv.x = acc[i][g * 4 + 0];
                vv.y = acc[i][g * 4 + 1];
                vv.z = acc[i][g * 4 + 2];
                vv.w = acc[i][g * 4 + 3];
                *(float4*)&Out[(size_t)row * H_DIM + c0] = vv;
            }
        }
    }
}

// ---------------------------------------------------------------------------
// Causal flash attention (fp32). BM=BN=128, 256 threads, 8x8 microtiles.
// Smem: Qs[d][m] 64KB | KP (Ks[d][j] then Ps[j][m] swizzled) 64KB | Vs[j][d] 64KB
// Row softmax == reference (global-max shift cancels; masked exp underflows to 0).
// Writes ctx in [b,s,h] layout directly.
// ---------------------------------------------------------------------------
__global__ void __launch_bounds__(256) flash_attn()
{
    extern __shared__ float sm[];
    float* Qs = sm;             // 128*128
    float* KP = sm + 16384;     // 128*128
    float* Vs = sm + 32768;     // 128*128

    const int tid = threadIdx.x;
    const int tx = tid & 15;
    const int ty = tid >> 4;
    const int qb = (int)(gridDim.x - 1) - (int)blockIdx.x;  // longest blocks first
    const int bh = blockIdx.y;

    const float* qT = g_qT + (size_t)bh * HDIM * S_LEN;
    const float* kT = g_kT + (size_t)bh * HDIM * S_LEN;
    const float* vp = g_v  + (size_t)bh * S_LEN * HDIM;

    // Load Q tile (already scaled by 1/sqrt(HD)): Qs[d][m]
#pragma unroll
    for (int i = 0; i < 16; i++) {
        int idx = tid + i * 256;
        int d = idx >> 5;
        int m4 = (idx & 31) << 2;
        *(float4*)&Qs[d * 128 + m4] =
            *(const float4*)&qT[(size_t)d * S_LEN + qb * 128 + m4];
    }

    float o[8][8];
    float Mr[8], Lr[8];
#pragma unroll
    for (int i = 0; i < 8; i++) {
        Mr[i] = -1e30f;
        Lr[i] = 0.0f;
#pragma unroll
        for (int j = 0; j < 8; j++) o[i][j] = 0.0f;
    }

    int ridx[8], jidx[8];
#pragma unroll
    for (int i = 0; i < 8; i++) ridx[i] = (i < 4) ? (ty * 4 + i) : (64 + ty * 4 + (i - 4));
#pragma unroll
    for (int j = 0; j < 8; j++) jidx[j] = (j < 4) ? (tx * 4 + j) : (64 + tx * 4 + (j - 4));

    for (int kb = 0; kb <= qb; kb++) {
        // Load K (d-major) and V (j-major) tiles
#pragma unroll
        for (int i = 0; i < 16; i++) {
            int idx = tid + i * 256;
            int r = idx >> 5;
            int c4 = (idx & 31) << 2;
            *(float4*)&KP[r * 128 + c4] =
                *(const float4*)&kT[(size_t)r * S_LEN + kb * 128 + c4];
            *(float4*)&Vs[r * 128 + c4] =
                *(const float4*)&vp[(size_t)(kb * 128 + r) * HDIM + c4];
        }
        __syncthreads();

        // S = Q K^T  (contraction over d)
        float s[8][8];
#pragma unroll
        for (int i = 0; i < 8; i++)
#pragma unroll
            for (int j = 0; j < 8; j++) s[i][j] = 0.0f;

#pragma unroll 8
        for (int d = 0; d < 128; d++) {
            float4 a0 = *(const float4*)&Qs[d * 128 + ty * 4];
            float4 a1 = *(const float4*)&Qs[d * 128 + 64 + ty * 4];
            float4 b0 = *(const float4*)&KP[d * 128 + tx * 4];
            float4 b1 = *(const float4*)&KP[d * 128 + 64 + tx * 4];
            float am[8] = {a0.x, a0.y, a0.z, a0.w, a1.x, a1.y, a1.z, a1.w};
            float bn[8] = {b0.x, b0.y, b0.z, b0.w, b1.x, b1.y, b1.z, b1.w};
#pragma unroll
            for (int i = 0; i < 8; i++)
#pragma unroll
                for (int j = 0; j < 8; j++)
                    s[i][j] += am[i] * bn[j];
        }
        __syncthreads();   // all threads done reading Ks (buffer becomes Ps)

        // Causal mask on diagonal block
        if (kb == qb) {
#pragma unroll
            for (int i = 0; i < 8; i++)
#pragma unroll
                for (int j = 0; j < 8; j++)
                    if (jidx[j] > ridx[i]) s[i][j] = -1e30f;
        }

        // Online softmax update (rows owned by same half-warp across tx)
#pragma unroll
        for (int i = 0; i < 8; i++) {
            float mx = s[i][0];
#pragma unroll
            for (int j = 1; j < 8; j++) mx = fmaxf(mx, s[i][j]);
            mx = fmaxf(mx, __shfl_xor_sync(0xffffffffu, mx, 8));
            mx = fmaxf(mx, __shfl_xor_sync(0xffffffffu, mx, 4));
            mx = fmaxf(mx, __shfl_xor_sync(0xffffffffu, mx, 2));
            mx = fmaxf(mx, __shfl_xor_sync(0xffffffffu, mx, 1));

            float mnew = fmaxf(Mr[i], mx);
            float corr = __expf(Mr[i] - mnew);
            Mr[i] = mnew;

            float rsum = 0.0f;
#pragma unroll
            for (int j = 0; j < 8; j++) {
                float p = __expf(s[i][j] - mnew);
                s[i][j] = p;
                rsum += p;
            }
            rsum += __shfl_xor_sync(0xffffffffu, rsum, 8);
            rsum += __shfl_xor_sync(0xffffffffu, rsum, 4);
            rsum += __shfl_xor_sync(0xffffffffu, rsum, 2);
            rsum += __shfl_xor_sync(0xffffffffu, rsum, 1);

            Lr[i] = Lr[i] * corr + rsum;
#pragma unroll
            for (int j = 0; j < 8; j++) o[i][j] *= corr;
        }

        // Store P as Ps[j][m] with XOR swizzle (reduces STS conflicts)
#pragma unroll
        for (int j = 0; j < 8; j++) {
            int jj = jidx[j];
            int swz = ((jj >> 2) & 7) << 2;
            int c0 = (ty * 4) ^ swz;
            float4 v0 = {s[0][j], s[1][j], s[2][j], s[3][j]};
            float4 v1 = {s[4][j], s[5][j], s[6][j], s[7][j]};
            *(float4*)&KP[jj * 128 + c0]      = v0;
            *(float4*)&KP[jj * 128 + 64 + c0] = v1;
        }
        __syncthreads();

        // O += P V  (contraction over j)
#pragma unroll 4
        for (int j = 0; j < 128; j++) {
            int swz = ((j >> 2) & 7) << 2;
            int c0 = (ty * 4) ^ swz;
            float4 a0 = *(const float4*)&KP[j * 128 + c0];
            float4 a1 = *(const float4*)&KP[j * 128 + 64 + c0];
            float4 b0 = *(const float4*)&Vs[j * 128 + tx * 4];
            float4 b1 = *(const float4*)&Vs[j * 128 + 64 + tx * 4];
            float am[8] = {a0.x, a0.y, a0.z, a0.w, a1.x, a1.y, a1.z, a1.w};
            float bn[8] = {b0.x, b0.y, b0.z, b0.w, b1.x, b1.y, b1.z, b1.w};
#pragma unroll
            for (int i = 0; i < 8; i++)
#pragma unroll
                for (int jn = 0; jn < 8; jn++)
                    o[i][jn] += am[i] * bn[jn];
        }
        __syncthreads();   // done reading Ps/Vs before next tile load
    }

    // Normalize and write ctx in [b, s, h] layout
    const int b = bh >> 4;
    const int n = bh & 15;
#pragma unroll
    for (int i = 0; i < 8; i++) {
        float inv = 1.0f / Lr[i];
        int srow = qb * 128 + ridx[i];
        float* dst = g_ctx + ((size_t)b * S_LEN + srow) * H_DIM + n * HDIM;
#pragma unroll
        for (int g = 0; g < 2; g++) {
            int c0 = g * 64 + tx * 4;
            float4 vv;
            vv.x = o[i][g * 4 + 0] * inv;
            vv.y = o[i][g * 4 + 1] * inv;
            vv.z = o[i][g * 4 + 2] * inv;
            vv.w = o[i][g * 4 + 3] * inv;
            *(float4*)&dst[c0] = vv;
        }
    }
}

// ---------------------------------------------------------------------------
extern "C" void kernel_launch(void* const* d_in, const int* in_sizes, int n_in,
                              void* d_out, int out_size)
{
    (void)in_sizes; (void)n_in; (void)out_size;
    const float* hidden  = (const float*)d_in[0];
    // d_in[1] = ltor_mask (causal tril) — structure exploited directly
    const float* w_qkv   = (const float*)d_in[2];
    const float* b_qkv   = (const float*)d_in[3];
    const float* w_dense = (const float*)d_in[4];
    const float* b_dense = (const float*)d_in[5];
    float* out = (float*)d_out;

    cudaFuncSetAttribute(flash_attn,
                         cudaFuncAttributeMaxDynamicSharedMemorySize, 196608);

    // 1) QKV GEMM + head scatter: [4096,2048] @ [6144,2048]^T
    sgemm_nt<0><<<dim3(48, 32), 256>>>(hidden, w_qkv, b_qkv, nullptr);

    // 2) Causal flash attention over 32 (b,head) pairs x 16 q-blocks
    flash_attn<<<dim3(16, 32), 256, 196608>>>();

    // 3) Dense projection: [4096,2048] @ [2048,2048]^T
    sgemm_nt<1><<<dim3(16, 32), 256>>>(hidden /*ignored*/, w_dense, b_dense, out);
}

// round 12
// speedup vs baseline: 1.6619x; 1.6619x over previous
#include <cuda_runtime.h>
#include <cstdint>
#include <cstddef>

// Problem constants (B=2, S=2048, H=2048, N=16 heads, HN=128)
#define S_LEN 2048
#define H_DIM 2048
#define NHEAD 16
#define HDIM  128
static __device__ __constant__ float kRSqrtHD = 0.08838834764831845f; // 1/sqrt(128)

// Scratch (device globals — allowed; no runtime allocation)
__device__ float g_qT [32u * 128u * 2048u];   // [b*16+n][d][s]   32 MB
__device__ float g_kT [32u * 128u * 2048u];   // [b*16+n][d][s]   32 MB
__device__ float g_v  [32u * 2048u * 128u];   // [b*16+n][s][d]   32 MB
__device__ float g_ctx[2u * 2048u * 2048u];   // [b][s][h]        32 MB

// ---------------------------------------------------------------------------
// Helpers (NO tcgen05/TMA — build targets plain sm_103, arch-'a' features
// are unavailable; use arch-neutral mma.sync/ldmatrix instead)
// ---------------------------------------------------------------------------
__device__ __forceinline__ uint32_t smem_u32(const void* p) {
    uint32_t a;
    asm("{ .reg .u64 t; cvta.to.shared.u64 t, %1; cvt.u32.u64 %0, t; }"
        : "=r"(a) : "l"(p));
    return a;
}
__device__ __forceinline__ uint32_t f2tf32(float f) {
    uint32_t u;
    asm("cvt.rna.tf32.f32 %0, %1;" : "=r"(u) : "f"(f));
    return u;
}
#define SWZ(o) ((o) ^ (((o) >> 3) & 0x70))

__device__ __forceinline__ void sts_tf32(uint32_t addr, float4 v) {
    uint32_t x = f2tf32(v.x), y = f2tf32(v.y), z = f2tf32(v.z), w = f2tf32(v.w);
    asm volatile("st.shared.v4.b32 [%0], {%1, %2, %3, %4};"
                 :: "r"(addr), "r"(x), "r"(y), "r"(z), "r"(w) : "memory");
}

__device__ __forceinline__ void ldsm_x4(uint32_t* r, uint32_t addr) {
    asm volatile("ldmatrix.sync.aligned.m8n8.x4.shared.b16 {%0,%1,%2,%3}, [%4];"
                 : "=r"(r[0]), "=r"(r[1]), "=r"(r[2]), "=r"(r[3])
                 : "r"(addr));
}

__device__ __forceinline__ void mma_tf32(float* c, const uint32_t* a, const uint32_t* b) {
    asm volatile(
        "mma.sync.aligned.m16n8k8.row.col.f32.tf32.tf32.f32 "
        "{%0,%1,%2,%3}, {%4,%5,%6,%7}, {%8,%9}, {%0,%1,%2,%3};"
        : "+f"(c[0]), "+f"(c[1]), "+f"(c[2]), "+f"(c[3])
        : "r"(a[0]), "r"(a[1]), "r"(a[2]), "r"(a[3]),
          "r"(b[0]), "r"(b[1]));
}

// ---------------------------------------------------------------------------
// tf32 mma.sync GEMM: C[M,*] = A[M,2048] @ W[Ncols,2048]^T + bias
// CTA 128x128, K-chunk 32, double-buffered SW128 smem, 8 warps (2x4),
// warp tile 64x32 (4x4 m16n8k8 tiles), fp32 register accumulators.
// MODE 0: QKV epilogue (scatter into g_qT/g_kT/g_v, q scaled by 1/sqrt(HD))
// MODE 1: dense epilogue (A is g_ctx; row-major store to Out)
// ---------------------------------------------------------------------------
template <int MODE>
__global__ void __launch_bounds__(256) gemm_mma(
    const float* __restrict__ Ain,
    const float* __restrict__ W,
    const float* __restrict__ bias,
    float* __restrict__ Out)
{
    constexpr int K = 2048, CK = 32, NC = K / CK;  // 64 chunks
    extern __shared__ char dynsm[];
    const uint32_t sbase = smem_u32(dynsm);
    // layout: A0 @0 (16K) | B0 @16K | A1 @32K | B1 @48K

    const int tid  = threadIdx.x;
    const int lane = tid & 31;
    const int wid  = tid >> 5;
    const int wm   = wid >> 2;   // 0..1
    const int wn   = wid & 3;    // 0..3
    const int rowBase = blockIdx.y * 128;
    const int colBase = blockIdx.x * 128;
    const float* Aeff = (MODE == 1) ? (const float*)g_ctx : Ain;

    // ---- loader mapping: 2 threads per row, 16 floats (4 x float4) each ----
    const int lrow = tid >> 1;                 // 0..127
    const int lcol = (tid & 1) * 16;           // float offset
    const float* aP = Aeff + (size_t)(rowBase + lrow) * K + lcol;
    const float* bP = W    + (size_t)(colBase + lrow) * K + lcol;
    uint32_t stoff[4];
#pragma unroll
    for (int g = 0; g < 4; g++)
        stoff[g] = SWZ((uint32_t)lrow * 128u + (uint32_t)(lcol + 4 * g) * 4u);

    // ---- compute-lane ldmatrix constants ----
    const int xorv  = lane & 7;
    const int aRow  = ((lane >> 3) & 1) * 8 + (lane & 7); // + wm*64 + mt*16
    const int aGoff = lane >> 4;                          // 0/1
    const int bRow  = (lane >> 4) * 8 + (lane & 7);       // + wn*32 + np*16
    const int bGoff = (lane >> 3) & 1;                    // 0/1

    float acc[4][4][4];
#pragma unroll
    for (int mt = 0; mt < 4; mt++)
#pragma unroll
        for (int nt = 0; nt < 4; nt++)
#pragma unroll
            for (int e = 0; e < 4; e++) acc[mt][nt][e] = 0.0f;

    // prologue: prefetch chunk 0
    float4 ra[4], rb[4];
#pragma unroll
    for (int g = 0; g < 4; g++) {
        ra[g] = *(const float4*)(aP + 4 * g);
        rb[g] = *(const float4*)(bP + 4 * g);
    }

    for (int c = 0; c < NC; c++) {
        const uint32_t Ab = sbase + (uint32_t)(c & 1) * 32768u;
        const uint32_t Bb = Ab + 16384u;

        // store chunk c (cvt.rna to tf32)
#pragma unroll
        for (int g = 0; g < 4; g++) {
            sts_tf32(Ab + stoff[g], ra[g]);
            sts_tf32(Bb + stoff[g], rb[g]);
        }
        __syncthreads();

        // prefetch chunk c+1
        if (c + 1 < NC) {
            const float* ap2 = aP + (size_t)(c + 1) * CK;
            const float* bp2 = bP + (size_t)(c + 1) * CK;
#pragma unroll
            for (int g = 0; g < 4; g++) {
                ra[g] = *(const float4*)(ap2 + 4 * g);
                rb[g] = *(const float4*)(bp2 + 4 * g);
            }
        }

        // compute chunk c
        const uint32_t aBase = Ab + (uint32_t)(wm * 64 + aRow) * 128u;
        const uint32_t bBase = Bb + (uint32_t)(wn * 32 + bRow) * 128u;
#pragma unroll
        for (int ks = 0; ks < 4; ks++) {
            uint32_t afr[4][4], bfr[2][4];
            const uint32_t gA = (uint32_t)(((ks * 2 + aGoff) ^ xorv) * 16);
            const uint32_t gB = (uint32_t)(((ks * 2 + bGoff) ^ xorv) * 16);
#pragma unroll
            for (int mt = 0; mt < 4; mt++)
                ldsm_x4(afr[mt], aBase + (uint32_t)mt * 2048u + gA);
#pragma unroll
            for (int np = 0; np < 2; np++)
                ldsm_x4(bfr[np], bBase + (uint32_t)np * 2048u + gB);
#pragma unroll
            for (int mt = 0; mt < 4; mt++)
#pragma unroll
                for (int nt = 0; nt < 4; nt++)
                    mma_tf32(acc[mt][nt], afr[mt], &bfr[nt >> 1][(nt & 1) * 2]);
        }
        __syncthreads();
    }

    // ---------------- epilogue ----------------
    const int part = colBase >> 11;            // MODE 0: 0=q 1=k 2=v
    const int head = (colBase & 2047) >> 7;
    const int b    = rowBase >> 11;

#pragma unroll
    for (int mt = 0; mt < 4; mt++) {
        const int r_lo = rowBase + wm * 64 + mt * 16 + (lane >> 2);
#pragma unroll
        for (int nt = 0; nt < 4; nt++) {
            const int j = colBase + wn * 32 + nt * 8 + 2 * (lane & 3);
            const float bj0 = bias[j], bj1 = bias[j + 1];
            float v00 = acc[mt][nt][0] + bj0;
            float v01 = acc[mt][nt][1] + bj1;
            float v10 = acc[mt][nt][2] + bj0;
            float v11 = acc[mt][nt][3] + bj1;

            if (MODE == 1) {
                float2 lo = {v00, v01}, hi = {v10, v11};
                *(float2*)&Out[(size_t)r_lo * H_DIM + j]       = lo;
                *(float2*)&Out[(size_t)(r_lo + 8) * H_DIM + j] = hi;
            } else {
                const int s = r_lo & 2047;
                const int d = j & 127;
                if (part < 2) {
                    const float sc = part ? 1.0f : kRSqrtHD;
                    float* dst = (part ? g_kT : g_qT)
                               + ((size_t)(b * NHEAD + head) * HDIM) * (size_t)S_LEN;
                    dst[(size_t)d       * S_LEN + s]     = v00 * sc;
                    dst[(size_t)(d + 1) * S_LEN + s]     = v01 * sc;
                    dst[(size_t)d       * S_LEN + s + 8] = v10 * sc;
                    dst[(size_t)(d + 1) * S_LEN + s + 8] = v11 * sc;
                } else {
                    float* dst = g_v + ((size_t)(b * NHEAD + head) * S_LEN) * HDIM;
                    float2 lo = {v00, v01}, hi = {v10, v11};
                    *(float2*)&dst[(size_t)s * HDIM + d]       = lo;
                    *(float2*)&dst[(size_t)(s + 8) * HDIM + d] = hi;
                }
            }
        }
    }
}

// ---------------------------------------------------------------------------
// Causal flash attention (fp32) — unchanged from passing Round 8 version.
// ---------------------------------------------------------------------------
__global__ void __launch_bounds__(256) flash_attn()
{
    extern __shared__ float sm[];
    float* Qs = sm;             // 128*128
    float* KP = sm + 16384;     // 128*128
    float* Vs = sm + 32768;     // 128*128

    const int tid = threadIdx.x;
    const int tx = tid & 15;
    const int ty = tid >> 4;
    const int qb = (int)(gridDim.x - 1) - (int)blockIdx.x;  // longest blocks first
    const int bh = blockIdx.y;

    const float* qT = g_qT + (size_t)bh * HDIM * S_LEN;
    const float* kT = g_kT + (size_t)bh * HDIM * S_LEN;
    const float* vp = g_v  + (size_t)bh * S_LEN * HDIM;

#pragma unroll
    for (int i = 0; i < 16; i++) {
        int idx = tid + i * 256;
        int d = idx >> 5;
        int m4 = (idx & 31) << 2;
        *(float4*)&Qs[d * 128 + m4] =
            *(const float4*)&qT[(size_t)d * S_LEN + qb * 128 + m4];
    }

    float o[8][8];
    float Mr[8], Lr[8];
#pragma unroll
    for (int i = 0; i < 8; i++) {
        Mr[i] = -1e30f;
        Lr[i] = 0.0f;
#pragma unroll
        for (int j = 0; j < 8; j++) o[i][j] = 0.0f;
    }

    int ridx[8], jidx[8];
#pragma unroll
    for (int i = 0; i < 8; i++) ridx[i] = (i < 4) ? (ty * 4 + i) : (64 + ty * 4 + (i - 4));
#pragma unroll
    for (int j = 0; j < 8; j++) jidx[j] = (j < 4) ? (tx * 4 + j) : (64 + tx * 4 + (j - 4));

    for (int kb = 0; kb <= qb; kb++) {
#pragma unroll
        for (int i = 0; i < 16; i++) {
            int idx = tid + i * 256;
            int r = idx >> 5;
            int c4 = (idx & 31) << 2;
            *(float4*)&KP[r * 128 + c4] =
                *(const float4*)&kT[(size_t)r * S_LEN + kb * 128 + c4];
            *(float4*)&Vs[r * 128 + c4] =
                *(const float4*)&vp[(size_t)(kb * 128 + r) * HDIM + c4];
        }
        __syncthreads();

        float s[8][8];
#pragma unroll
        for (int i = 0; i < 8; i++)
#pragma unroll
            for (int j = 0; j < 8; j++) s[i][j] = 0.0f;

#pragma unroll 8
        for (int d = 0; d < 128; d++) {
            float4 a0 = *(const float4*)&Qs[d * 128 + ty * 4];
            float4 a1 = *(const float4*)&Qs[d * 128 + 64 + ty * 4];
            float4 b0 = *(const float4*)&KP[d * 128 + tx * 4];
            float4 b1 = *(const float4*)&KP[d * 128 + 64 + tx * 4];
            float am[8] = {a0.x, a0.y, a0.z, a0.w, a1.x, a1.y, a1.z, a1.w};
            float bn[8] = {b0.x, b0.y, b0.z, b0.w, b1.x, b1.y, b1.z, b1.w};
#pragma unroll
            for (int i = 0; i < 8; i++)
#pragma unroll
                for (int j = 0; j < 8; j++)
                    s[i][j] += am[i] * bn[j];
        }
        __syncthreads();

        if (kb == qb) {
#pragma unroll
            for (int i = 0; i < 8; i++)
#pragma unroll
                for (int j = 0; j < 8; j++)
                    if (jidx[j] > ridx[i]) s[i][j] = -1e30f;
        }

#pragma unroll
        for (int i = 0; i < 8; i++) {
            float mx = s[i][0];
#pragma unroll
            for (int j = 1; j < 8; j++) mx = fmaxf(mx, s[i][j]);
            mx = fmaxf(mx, __shfl_xor_sync(0xffffffffu, mx, 8));
            mx = fmaxf(mx, __shfl_xor_sync(0xffffffffu, mx, 4));
            mx = fmaxf(mx, __shfl_xor_sync(0xffffffffu, mx, 2));
            mx = fmaxf(mx, __shfl_xor_sync(0xffffffffu, mx, 1));

            float mnew = fmaxf(Mr[i], mx);
            float corr = __expf(Mr[i] - mnew);
            Mr[i] = mnew;

            float rsum = 0.0f;
#pragma unroll
            for (int j = 0; j < 8; j++) {
                float p = __expf(s[i][j] - mnew);
                s[i][j] = p;
                rsum += p;
            }
            rsum += __shfl_xor_sync(0xffffffffu, rsum, 8);
            rsum += __shfl_xor_sync(0xffffffffu, rsum, 4);
            rsum += __shfl_xor_sync(0xffffffffu, rsum, 2);
            rsum += __shfl_xor_sync(0xffffffffu, rsum, 1);

            Lr[i] = Lr[i] * corr + rsum;
#pragma unroll
            for (int j = 0; j < 8; j++) o[i][j] *= corr;
        }

#pragma unroll
        for (int j = 0; j < 8; j++) {
            int jj = jidx[j];
            int swz = ((jj >> 2) & 7) << 2;
            int c0 = (ty * 4) ^ swz;
            float4 v0 = {s[0][j], s[1][j], s[2][j], s[3][j]};
            float4 v1 = {s[4][j], s[5][j], s[6][j], s[7][j]};
            *(float4*)&KP[jj * 128 + c0]      = v0;
            *(float4*)&KP[jj * 128 + 64 + c0] = v1;
        }
        __syncthreads();

#pragma unroll 4
        for (int j = 0; j < 128; j++) {
            int swz = ((j >> 2) & 7) << 2;
            int c0 = (ty * 4) ^ swz;
            float4 a0 = *(const float4*)&KP[j * 128 + c0];
            float4 a1 = *(const float4*)&KP[j * 128 + 64 + c0];
            float4 b0 = *(const float4*)&Vs[j * 128 + tx * 4];
            float4 b1 = *(const float4*)&Vs[j * 128 + 64 + tx * 4];
            float am[8] = {a0.x, a0.y, a0.z, a0.w, a1.x, a1.y, a1.z, a1.w};
            float bn[8] = {b0.x, b0.y, b0.z, b0.w, b1.x, b1.y, b1.z, b1.w};
#pragma unroll
            for (int i = 0; i < 8; i++)
#pragma unroll
                for (int jn = 0; jn < 8; jn++)
                    o[i][jn] += am[i] * bn[jn];
        }
        __syncthreads();
    }

    const int b = bh >> 4;
    const int n = bh & 15;
#pragma unroll
    for (int i = 0; i < 8; i++) {
        float inv = 1.0f / Lr[i];
        int srow = qb * 128 + ridx[i];
        float* dst = g_ctx + ((size_t)b * S_LEN + srow) * H_DIM + n * HDIM;
#pragma unroll
        for (int g = 0; g < 2; g++) {
            int c0 = g * 64 + tx * 4;
            float4 vv;
            vv.x = o[i][g * 4 + 0] * inv;
            vv.y = o[i][g * 4 + 1] * inv;
            vv.z = o[i][g * 4 + 2] * inv;
            vv.w = o[i][g * 4 + 3] * inv;
            *(float4*)&dst[c0] = vv;
        }
    }
}

// ---------------------------------------------------------------------------
extern "C" void kernel_launch(void* const* d_in, const int* in_sizes, int n_in,
                              void* d_out, int out_size)
{
    (void)in_sizes; (void)n_in; (void)out_size;
    const float* hidden  = (const float*)d_in[0];
    // d_in[1] = ltor_mask (causal tril) — structure exploited directly
    const float* w_qkv   = (const float*)d_in[2];
    const float* b_qkv   = (const float*)d_in[3];
    const float* w_dense = (const float*)d_in[4];
    const float* b_dense = (const float*)d_in[5];
    float* out = (float*)d_out;

    const int GEMM_SMEM = 65536;
    cudaFuncSetAttribute(gemm_mma<0>, cudaFuncAttributeMaxDynamicSharedMemorySize, GEMM_SMEM);
    cudaFuncSetAttribute(gemm_mma<1>, cudaFuncAttributeMaxDynamicSharedMemorySize, GEMM_SMEM);
    cudaFuncSetAttribute(flash_attn,  cudaFuncAttributeMaxDynamicSharedMemorySize, 196608);

    // 1) QKV: [4096,2048] @ [6144,2048]^T, tiles 128x128
    gemm_mma<0><<<dim3(48, 32), 256, GEMM_SMEM>>>(hidden, w_qkv, b_qkv, nullptr);

    // 2) Causal flash attention over 32 (b,head) pairs x 16 q-blocks
    flash_attn<<<dim3(16, 32), 256, 196608>>>();

    // 3) Dense: [4096,2048] @ [2048,2048]^T
    gemm_mma<1><<<dim3(16, 32), 256, GEMM_SMEM>>>(nullptr, w_dense, b_dense, out);
}

// round 13
// speedup vs baseline: 1.6621x; 1.0001x over previous
#include <cuda_runtime.h>
#include <cstdint>
#include <cstddef>

// Problem constants (B=2, S=2048, H=2048, N=16 heads, HN=128)
#define S_LEN 2048
#define H_DIM 2048
#define NHEAD 16
#define HDIM  128
static __device__ __constant__ float kRSqrtHD = 0.08838834764831845f; // 1/sqrt(128)

// Scratch (device globals — allowed; no runtime allocation)
__device__ float g_qT [32u * 128u * 2048u];   // [b*16+n][d][s]   32 MB
__device__ float g_kT [32u * 128u * 2048u];   // [b*16+n][d][s]   32 MB
__device__ float g_v  [32u * 2048u * 128u];   // [b*16+n][s][d]   32 MB
__device__ float g_ctx[2u * 2048u * 2048u];   // [b][s][h]        32 MB

// ---------------------------------------------------------------------------
// Helpers (NO tcgen05/TMA — build targets plain sm_103, arch-'a' features
// are unavailable; use arch-neutral mma.sync/ldmatrix instead)
// ---------------------------------------------------------------------------
__device__ __forceinline__ uint32_t smem_u32(const void* p) {
    uint32_t a;
    asm("{ .reg .u64 t; cvta.to.shared.u64 t, %1; cvt.u32.u64 %0, t; }"
        : "=r"(a) : "l"(p));
    return a;
}
__device__ __forceinline__ uint32_t f2tf32(float f) {
    uint32_t u;
    asm("cvt.rna.tf32.f32 %0, %1;" : "=r"(u) : "f"(f));
    return u;
}
#define SWZ(o) ((o) ^ (((o) >> 3) & 0x70))

__device__ __forceinline__ void sts_tf32(uint32_t addr, float4 v) {
    uint32_t x = f2tf32(v.x), y = f2tf32(v.y), z = f2tf32(v.z), w = f2tf32(v.w);
    asm volatile("st.shared.v4.b32 [%0], {%1, %2, %3, %4};"
                 :: "r"(addr), "r"(x), "r"(y), "r"(z), "r"(w) : "memory");
}

__device__ __forceinline__ void ldsm_x4(uint32_t* r, uint32_t addr) {
    asm volatile("ldmatrix.sync.aligned.m8n8.x4.shared.b16 {%0,%1,%2,%3}, [%4];"
                 : "=r"(r[0]), "=r"(r[1]), "=r"(r[2]), "=r"(r[3])
                 : "r"(addr));
}

__device__ __forceinline__ void mma_tf32(float* c, const uint32_t* a, const uint32_t* b) {
    asm volatile(
        "mma.sync.aligned.m16n8k8.row.col.f32.tf32.tf32.f32 "
        "{%0,%1,%2,%3}, {%4,%5,%6,%7}, {%8,%9}, {%0,%1,%2,%3};"
        : "+f"(c[0]), "+f"(c[1]), "+f"(c[2]), "+f"(c[3])
        : "r"(a[0]), "r"(a[1]), "r"(a[2]), "r"(a[3]),
          "r"(b[0]), "r"(b[1]));
}

// ---------------------------------------------------------------------------
// tf32 mma.sync GEMM: C[M,*] = A[M,2048] @ W[Ncols,2048]^T + bias
// CTA 128x128, K-chunk 32, double-buffered SW128 smem, 8 warps (2x4),
// warp tile 64x32 (4x4 m16n8k8 tiles), fp32 register accumulators.
// MODE 0: QKV epilogue (scatter into g_qT/g_kT/g_v, q scaled by 1/sqrt(HD))
// MODE 1: dense epilogue (A is g_ctx; row-major store to Out)
// ---------------------------------------------------------------------------
template <int MODE>
__global__ void __launch_bounds__(256) gemm_mma(
    const float* __restrict__ Ain,
    const float* __restrict__ W,
    const float* __restrict__ bias,
    float* __restrict__ Out)
{
    constexpr int K = 2048, CK = 32, NC = K / CK;  // 64 chunks
    extern __shared__ char dynsm[];
    const uint32_t sbase = smem_u32(dynsm);
    // layout: A0 @0 (16K) | B0 @16K | A1 @32K | B1 @48K

    const int tid  = threadIdx.x;
    const int lane = tid & 31;
    const int wid  = tid >> 5;
    const int wm   = wid >> 2;   // 0..1
    const int wn   = wid & 3;    // 0..3
    const int rowBase = blockIdx.y * 128;
    const int colBase = blockIdx.x * 128;
    const float* Aeff = (MODE == 1) ? (const float*)g_ctx : Ain;

    // ---- loader mapping: 2 threads per row, 16 floats (4 x float4) each ----
    const int lrow = tid >> 1;                 // 0..127
    const int lcol = (tid & 1) * 16;           // float offset
    const float* aP = Aeff + (size_t)(rowBase + lrow) * K + lcol;
    const float* bP = W    + (size_t)(colBase + lrow) * K + lcol;
    uint32_t stoff[4];
#pragma unroll
    for (int g = 0; g < 4; g++)
        stoff[g] = SWZ((uint32_t)lrow * 128u + (uint32_t)(lcol + 4 * g) * 4u);

    // ---- compute-lane ldmatrix constants ----
    const int xorv  = lane & 7;
    const int aRow  = ((lane >> 3) & 1) * 8 + (lane & 7); // + wm*64 + mt*16
    const int aGoff = lane >> 4;                          // 0/1
    const int bRow  = (lane >> 4) * 8 + (lane & 7);       // + wn*32 + np*16
    const int bGoff = (lane >> 3) & 1;                    // 0/1

    float acc[4][4][4];
#pragma unroll
    for (int mt = 0; mt < 4; mt++)
#pragma unroll
        for (int nt = 0; nt < 4; nt++)
#pragma unroll
            for (int e = 0; e < 4; e++) acc[mt][nt][e] = 0.0f;

    // prologue: prefetch chunk 0
    float4 ra[4], rb[4];
#pragma unroll
    for (int g = 0; g < 4; g++) {
        ra[g] = *(const float4*)(aP + 4 * g);
        rb[g] = *(const float4*)(bP + 4 * g);
    }

    for (int c = 0; c < NC; c++) {
        const uint32_t Ab = sbase + (uint32_t)(c & 1) * 32768u;
        const uint32_t Bb = Ab + 16384u;

        // store chunk c (cvt.rna to tf32)
#pragma unroll
        for (int g = 0; g < 4; g++) {
            sts_tf32(Ab + stoff[g], ra[g]);
            sts_tf32(Bb + stoff[g], rb[g]);
        }
        __syncthreads();

        // prefetch chunk c+1
        if (c + 1 < NC) {
            const float* ap2 = aP + (size_t)(c + 1) * CK;
            const float* bp2 = bP + (size_t)(c + 1) * CK;
#pragma unroll
            for (int g = 0; g < 4; g++) {
                ra[g] = *(const float4*)(ap2 + 4 * g);
                rb[g] = *(const float4*)(bp2 + 4 * g);
            }
        }

        // compute chunk c
        const uint32_t aBase = Ab + (uint32_t)(wm * 64 + aRow) * 128u;
        const uint32_t bBase = Bb + (uint32_t)(wn * 32 + bRow) * 128u;
#pragma unroll
        for (int ks = 0; ks < 4; ks++) {
            uint32_t afr[4][4], bfr[2][4];
            const uint32_t gA = (uint32_t)(((ks * 2 + aGoff) ^ xorv) * 16);
            const uint32_t gB = (uint32_t)(((ks * 2 + bGoff) ^ xorv) * 16);
#pragma unroll
            for (int mt = 0; mt < 4; mt++)
                ldsm_x4(afr[mt], aBase + (uint32_t)mt * 2048u + gA);
#pragma unroll
            for (int np = 0; np < 2; np++)
                ldsm_x4(bfr[np], bBase + (uint32_t)np * 2048u + gB);
#pragma unroll
            for (int mt = 0; mt < 4; mt++)
#pragma unroll
                for (int nt = 0; nt < 4; nt++)
                    mma_tf32(acc[mt][nt], afr[mt], &bfr[nt >> 1][(nt & 1) * 2]);
        }
        __syncthreads();
    }

    // ---------------- epilogue ----------------
    const int part = colBase >> 11;            // MODE 0: 0=q 1=k 2=v
    const int head = (colBase & 2047) >> 7;
    const int b    = rowBase >> 11;

#pragma unroll
    for (int mt = 0; mt < 4; mt++) {
        const int r_lo = rowBase + wm * 64 + mt * 16 + (lane >> 2);
#pragma unroll
        for (int nt = 0; nt < 4; nt++) {
            const int j = colBase + wn * 32 + nt * 8 + 2 * (lane & 3);
            const float bj0 = bias[j], bj1 = bias[j + 1];
            float v00 = acc[mt][nt][0] + bj0;
            float v01 = acc[mt][nt][1] + bj1;
            float v10 = acc[mt][nt][2] + bj0;
            float v11 = acc[mt][nt][3] + bj1;

            if (MODE == 1) {
                float2 lo = {v00, v01}, hi = {v10, v11};
                *(float2*)&Out[(size_t)r_lo * H_DIM + j]       = lo;
                *(float2*)&Out[(size_t)(r_lo + 8) * H_DIM + j] = hi;
            } else {
                const int s = r_lo & 2047;
                const int d = j & 127;
                if (part < 2) {
                    const float sc = part ? 1.0f : kRSqrtHD;
                    float* dst = (part ? g_kT : g_qT)
                               + ((size_t)(b * NHEAD + head) * HDIM) * (size_t)S_LEN;
                    dst[(size_t)d       * S_LEN + s]     = v00 * sc;
                    dst[(size_t)(d + 1) * S_LEN + s]     = v01 * sc;
                    dst[(size_t)d       * S_LEN + s + 8] = v10 * sc;
                    dst[(size_t)(d + 1) * S_LEN + s + 8] = v11 * sc;
                } else {
                    float* dst = g_v + ((size_t)(b * NHEAD + head) * S_LEN) * HDIM;
                    float2 lo = {v00, v01}, hi = {v10, v11};
                    *(float2*)&dst[(size_t)s * HDIM + d]       = lo;
                    *(float2*)&dst[(size_t)(s + 8) * HDIM + d] = hi;
                }
            }
        }
    }
}

// ---------------------------------------------------------------------------
// Causal flash attention (fp32) — unchanged from passing Round 8 version.
// ---------------------------------------------------------------------------
__global__ void __launch_bounds__(256) flash_attn()
{
    extern __shared__ float sm[];
    float* Qs = sm;             // 128*128
    float* KP = sm + 16384;     // 128*128
    float* Vs = sm + 32768;     // 128*128

    const int tid = threadIdx.x;
    const int tx = tid & 15;
    const int ty = tid >> 4;
    const int qb = (int)(gridDim.x - 1) - (int)blockIdx.x;  // longest blocks first
    const int bh = blockIdx.y;

    const float* qT = g_qT + (size_t)bh * HDIM * S_LEN;
    const float* kT = g_kT + (size_t)bh * HDIM * S_LEN;
    const float* vp = g_v  + (size_t)bh * S_LEN * HDIM;

#pragma unroll
    for (int i = 0; i < 16; i++) {
        int idx = tid + i * 256;
        int d = idx >> 5;
        int m4 = (idx & 31) << 2;
        *(float4*)&Qs[d * 128 + m4] =
            *(const float4*)&qT[(size_t)d * S_LEN + qb * 128 + m4];
    }

    float o[8][8];
    float Mr[8], Lr[8];
#pragma unroll
    for (int i = 0; i < 8; i++) {
        Mr[i] = -1e30f;
        Lr[i] = 0.0f;
#pragma unroll
        for (int j = 0; j < 8; j++) o[i][j] = 0.0f;
    }

    int ridx[8], jidx[8];
#pragma unroll
    for (int i = 0; i < 8; i++) ridx[i] = (i < 4) ? (ty * 4 + i) : (64 + ty * 4 + (i - 4));
#pragma unroll
    for (int j = 0; j < 8; j++) jidx[j] = (j < 4) ? (tx * 4 + j) : (64 + tx * 4 + (j - 4));

    for (int kb = 0; kb <= qb; kb++) {
#pragma unroll
        for (int i = 0; i < 16; i++) {
            int idx = tid + i * 256;
            int r = idx >> 5;
            int c4 = (idx & 31) << 2;
            *(float4*)&KP[r * 128 + c4] =
                *(const float4*)&kT[(size_t)r * S_LEN + kb * 128 + c4];
            *(float4*)&Vs[r * 128 + c4] =
                *(const float4*)&vp[(size_t)(kb * 128 + r) * HDIM + c4];
        }
        __syncthreads();

        float s[8][8];
#pragma unroll
        for (int i = 0; i < 8; i++)
#pragma unroll
            for (int j = 0; j < 8; j++) s[i][j] = 0.0f;

#pragma unroll 8
        for (int d = 0; d < 128; d++) {
            float4 a0 = *(const float4*)&Qs[d * 128 + ty * 4];
            float4 a1 = *(const float4*)&Qs[d * 128 + 64 + ty * 4];
            float4 b0 = *(const float4*)&KP[d * 128 + tx * 4];
            float4 b1 = *(const float4*)&KP[d * 128 + 64 + tx * 4];
            float am[8] = {a0.x, a0.y, a0.z, a0.w, a1.x, a1.y, a1.z, a1.w};
            float bn[8] = {b0.x, b0.y, b0.z, b0.w, b1.x, b1.y, b1.z, b1.w};
#pragma unroll
            for (int i = 0; i < 8; i++)
#pragma unroll
                for (int j = 0; j < 8; j++)
                    s[i][j] += am[i] * bn[j];
        }
        __syncthreads();

        if (kb == qb) {
#pragma unroll
            for (int i = 0; i < 8; i++)
#pragma unroll
                for (int j = 0; j < 8; j++)
                    if (jidx[j] > ridx[i]) s[i][j] = -1e30f;
        }

#pragma unroll
        for (int i = 0; i < 8; i++) {
            float mx = s[i][0];
#pragma unroll
            for (int j = 1; j < 8; j++) mx = fmaxf(mx, s[i][j]);
            mx = fmaxf(mx, __shfl_xor_sync(0xffffffffu, mx, 8));
            mx = fmaxf(mx, __shfl_xor_sync(0xffffffffu, mx, 4));
            mx = fmaxf(mx, __shfl_xor_sync(0xffffffffu, mx, 2));
            mx = fmaxf(mx, __shfl_xor_sync(0xffffffffu, mx, 1));

            float mnew = fmaxf(Mr[i], mx);
            float corr = __expf(Mr[i] - mnew);
            Mr[i] = mnew;

            float rsum = 0.0f;
#pragma unroll
            for (int j = 0; j < 8; j++) {
                float p = __expf(s[i][j] - mnew);
                s[i][j] = p;
                rsum += p;
            }
            rsum += __shfl_xor_sync(0xffffffffu, rsum, 8);
            rsum += __shfl_xor_sync(0xffffffffu, rsum, 4);
            rsum += __shfl_xor_sync(0xffffffffu, rsum, 2);
            rsum += __shfl_xor_sync(0xffffffffu, rsum, 1);

            Lr[i] = Lr[i] * corr + rsum;
#pragma unroll
            for (int j = 0; j < 8; j++) o[i][j] *= corr;
        }

#pragma unroll
        for (int j = 0; j < 8; j++) {
            int jj = jidx[j];
            int swz = ((jj >> 2) & 7) << 2;
            int c0 = (ty * 4) ^ swz;
            float4 v0 = {s[0][j], s[1][j], s[2][j], s[3][j]};
            float4 v1 = {s[4][j], s[5][j], s[6][j], s[7][j]};
            *(float4*)&KP[jj * 128 + c0]      = v0;
            *(float4*)&KP[jj * 128 + 64 + c0] = v1;
        }
        __syncthreads();

#pragma unroll 4
        for (int j = 0; j < 128; j++) {
            int swz = ((j >> 2) & 7) << 2;
            int c0 = (ty * 4) ^ swz;
            float4 a0 = *(const float4*)&KP[j * 128 + c0];
            float4 a1 = *(const float4*)&KP[j * 128 + 64 + c0];
            float4 b0 = *(const float4*)&Vs[j * 128 + tx * 4];
            float4 b1 = *(const float4*)&Vs[j * 128 + 64 + tx * 4];
            float am[8] = {a0.x, a0.y, a0.z, a0.w, a1.x, a1.y, a1.z, a1.w};
            float bn[8] = {b0.x, b0.y, b0.z, b0.w, b1.x, b1.y, b1.z, b1.w};
#pragma unroll
            for (int i = 0; i < 8; i++)
#pragma unroll
                for (int jn = 0; jn < 8; jn++)
                    o[i][jn] += am[i] * bn[jn];
        }
        __syncthreads();
    }

    const int b = bh >> 4;
    const int n = bh & 15;
#pragma unroll
    for (int i = 0; i < 8; i++) {
        float inv = 1.0f / Lr[i];
        int srow = qb * 128 + ridx[i];
        float* dst = g_ctx + ((size_t)b * S_LEN + srow) * H_DIM + n * HDIM;
#pragma unroll
        for (int g = 0; g < 2; g++) {
            int c0 = g * 64 + tx * 4;
            float4 vv;
            vv.x = o[i][g * 4 + 0] * inv;
            vv.y = o[i][g * 4 + 1] * inv;
            vv.z = o[i][g * 4 + 2] * inv;
            vv.w = o[i][g * 4 + 3] * inv;
            *(float4*)&dst[c0] = vv;
        }
    }
}

// ---------------------------------------------------------------------------
extern "C" void kernel_launch(void* const* d_in, const int* in_sizes, int n_in,
                              void* d_out, int out_size)
{
    (void)in_sizes; (void)n_in; (void)out_size;
    const float* hidden  = (const float*)d_in[0];
    // d_in[1] = ltor_mask (causal tril) — structure exploited directly
    const float* w_qkv   = (const float*)d_in[2];
    const float* b_qkv   = (const float*)d_in[3];
    const float* w_dense = (const float*)d_in[4];
    const float* b_dense = (const float*)d_in[5];
    float* out = (float*)d_out;

    const int GEMM_SMEM = 65536;
    cudaFuncSetAttribute(gemm_mma<0>, cudaFuncAttributeMaxDynamicSharedMemorySize, GEMM_SMEM);
    cudaFuncSetAttribute(gemm_mma<1>, cudaFuncAttributeMaxDynamicSharedMemorySize, GEMM_SMEM);
    cudaFuncSetAttribute(flash_attn,  cudaFuncAttributeMaxDynamicSharedMemorySize, 196608);

    // 1) QKV: [4096,2048] @ [6144,2048]^T, tiles 128x128
    gemm_mma<0><<<dim3(48, 32), 256, GEMM_SMEM>>>(hidden, w_qkv, b_qkv, nullptr);

    // 2) Causal flash attention over 32 (b,head) pairs x 16 q-blocks
    flash_attn<<<dim3(16, 32), 256, 196608>>>();

    // 3) Dense: [4096,2048] @ [2048,2048]^T
    gemm_mma<1><<<dim3(16, 32), 256, GEMM_SMEM>>>(nullptr, w_dense, b_dense, out);
}

// round 14
// speedup vs baseline: 1.6623x; 1.0001x over previous
#include <cuda_runtime.h>
#include <cstdint>
#include <cstddef>

// Problem constants (B=2, S=2048, H=2048, N=16 heads, HN=128)
#define S_LEN 2048
#define H_DIM 2048
#define NHEAD 16
#define HDIM  128
static __device__ __constant__ float kRSqrtHD = 0.08838834764831845f; // 1/sqrt(128)

// Scratch (device globals — allowed; no runtime allocation)
__device__ float g_qT [32u * 128u * 2048u];   // [b*16+n][d][s]   32 MB
__device__ float g_kT [32u * 128u * 2048u];   // [b*16+n][d][s]   32 MB
__device__ float g_v  [32u * 2048u * 128u];   // [b*16+n][s][d]   32 MB
__device__ float g_ctx[2u * 2048u * 2048u];   // [b][s][h]        32 MB

// ---------------------------------------------------------------------------
// Helpers (NO tcgen05/TMA — build targets plain sm_103, arch-'a' features
// are unavailable; use arch-neutral mma.sync/ldmatrix instead)
// ---------------------------------------------------------------------------
__device__ __forceinline__ uint32_t smem_u32(const void* p) {
    uint32_t a;
    asm("{ .reg .u64 t; cvta.to.shared.u64 t, %1; cvt.u32.u64 %0, t; }"
        : "=r"(a) : "l"(p));
    return a;
}
__device__ __forceinline__ uint32_t f2tf32(float f) {
    uint32_t u;
    asm("cvt.rna.tf32.f32 %0, %1;" : "=r"(u) : "f"(f));
    return u;
}
#define SWZ(o) ((o) ^ (((o) >> 3) & 0x70))

__device__ __forceinline__ void sts_tf32(uint32_t addr, float4 v) {
    uint32_t x = f2tf32(v.x), y = f2tf32(v.y), z = f2tf32(v.z), w = f2tf32(v.w);
    asm volatile("st.shared.v4.b32 [%0], {%1, %2, %3, %4};"
                 :: "r"(addr), "r"(x), "r"(y), "r"(z), "r"(w) : "memory");
}

__device__ __forceinline__ void ldsm_x4(uint32_t* r, uint32_t addr) {
    asm volatile("ldmatrix.sync.aligned.m8n8.x4.shared.b16 {%0,%1,%2,%3}, [%4];"
                 : "=r"(r[0]), "=r"(r[1]), "=r"(r[2]), "=r"(r[3])
                 : "r"(addr));
}

__device__ __forceinline__ void mma_tf32(float* c, const uint32_t* a, const uint32_t* b) {
    asm volatile(
        "mma.sync.aligned.m16n8k8.row.col.f32.tf32.tf32.f32 "
        "{%0,%1,%2,%3}, {%4,%5,%6,%7}, {%8,%9}, {%0,%1,%2,%3};"
        : "+f"(c[0]), "+f"(c[1]), "+f"(c[2]), "+f"(c[3])
        : "r"(a[0]), "r"(a[1]), "r"(a[2]), "r"(a[3]),
          "r"(b[0]), "r"(b[1]));
}

// ---------------------------------------------------------------------------
// tf32 mma.sync GEMM: C[M,*] = A[M,2048] @ W[Ncols,2048]^T + bias
// CTA 128x128, K-chunk 32, double-buffered SW128 smem, 8 warps (2x4),
// warp tile 64x32 (4x4 m16n8k8 tiles), fp32 register accumulators.
// MODE 0: QKV epilogue (scatter into g_qT/g_kT/g_v, q scaled by 1/sqrt(HD))
// MODE 1: dense epilogue (A is g_ctx; row-major store to Out)
// ---------------------------------------------------------------------------
template <int MODE>
__global__ void __launch_bounds__(256) gemm_mma(
    const float* __restrict__ Ain,
    const float* __restrict__ W,
    const float* __restrict__ bias,
    float* __restrict__ Out)
{
    constexpr int K = 2048, CK = 32, NC = K / CK;  // 64 chunks
    extern __shared__ char dynsm[];
    const uint32_t sbase = smem_u32(dynsm);
    // layout: A0 @0 (16K) | B0 @16K | A1 @32K | B1 @48K

    const int tid  = threadIdx.x;
    const int lane = tid & 31;
    const int wid  = tid >> 5;
    const int wm   = wid >> 2;   // 0..1
    const int wn   = wid & 3;    // 0..3
    const int rowBase = blockIdx.y * 128;
    const int colBase = blockIdx.x * 128;
    const float* Aeff = (MODE == 1) ? (const float*)g_ctx : Ain;

    // ---- loader mapping: 2 threads per row, 16 floats (4 x float4) each ----
    const int lrow = tid >> 1;                 // 0..127
    const int lcol = (tid & 1) * 16;           // float offset
    const float* aP = Aeff + (size_t)(rowBase + lrow) * K + lcol;
    const float* bP = W    + (size_t)(colBase + lrow) * K + lcol;
    uint32_t stoff[4];
#pragma unroll
    for (int g = 0; g < 4; g++)
        stoff[g] = SWZ((uint32_t)lrow * 128u + (uint32_t)(lcol + 4 * g) * 4u);

    // ---- compute-lane ldmatrix constants ----
    const int xorv  = lane & 7;
    const int aRow  = ((lane >> 3) & 1) * 8 + (lane & 7); // + wm*64 + mt*16
    const int aGoff = lane >> 4;                          // 0/1
    const int bRow  = (lane >> 4) * 8 + (lane & 7);       // + wn*32 + np*16
    const int bGoff = (lane >> 3) & 1;                    // 0/1

    float acc[4][4][4];
#pragma unroll
    for (int mt = 0; mt < 4; mt++)
#pragma unroll
        for (int nt = 0; nt < 4; nt++)
#pragma unroll
            for (int e = 0; e < 4; e++) acc[mt][nt][e] = 0.0f;

    // prologue: prefetch chunk 0
    float4 ra[4], rb[4];
#pragma unroll
    for (int g = 0; g < 4; g++) {
        ra[g] = *(const float4*)(aP + 4 * g);
        rb[g] = *(const float4*)(bP + 4 * g);
    }

    for (int c = 0; c < NC; c++) {
        const uint32_t Ab = sbase + (uint32_t)(c & 1) * 32768u;
        const uint32_t Bb = Ab + 16384u;

        // store chunk c (cvt.rna to tf32)
#pragma unroll
        for (int g = 0; g < 4; g++) {
            sts_tf32(Ab + stoff[g], ra[g]);
            sts_tf32(Bb + stoff[g], rb[g]);
        }
        __syncthreads();

        // prefetch chunk c+1
        if (c + 1 < NC) {
            const float* ap2 = aP + (size_t)(c + 1) * CK;
            const float* bp2 = bP + (size_t)(c + 1) * CK;
#pragma unroll
            for (int g = 0; g < 4; g++) {
                ra[g] = *(const float4*)(ap2 + 4 * g);
                rb[g] = *(const float4*)(bp2 + 4 * g);
            }
        }

        // compute chunk c
        const uint32_t aBase = Ab + (uint32_t)(wm * 64 + aRow) * 128u;
        const uint32_t bBase = Bb + (uint32_t)(wn * 32 + bRow) * 128u;
#pragma unroll
        for (int ks = 0; ks < 4; ks++) {
            uint32_t afr[4][4], bfr[2][4];
            const uint32_t gA = (uint32_t)(((ks * 2 + aGoff) ^ xorv) * 16);
            const uint32_t gB = (uint32_t)(((ks * 2 + bGoff) ^ xorv) * 16);
#pragma unroll
            for (int mt = 0; mt < 4; mt++)
                ldsm_x4(afr[mt], aBase + (uint32_t)mt * 2048u + gA);
#pragma unroll
            for (int np = 0; np < 2; np++)
                ldsm_x4(bfr[np], bBase + (uint32_t)np * 2048u + gB);
#pragma unroll
            for (int mt = 0; mt < 4; mt++)
#pragma unroll
                for (int nt = 0; nt < 4; nt++)
                    mma_tf32(acc[mt][nt], afr[mt], &bfr[nt >> 1][(nt & 1) * 2]);
        }
        __syncthreads();
    }

    // ---------------- epilogue ----------------
    const int part = colBase >> 11;            // MODE 0: 0=q 1=k 2=v
    const int head = (colBase & 2047) >> 7;
    const int b    = rowBase >> 11;

#pragma unroll
    for (int mt = 0; mt < 4; mt++) {
        const int r_lo = rowBase + wm * 64 + mt * 16 + (lane >> 2);
#pragma unroll
        for (int nt = 0; nt < 4; nt++) {
            const int j = colBase + wn * 32 + nt * 8 + 2 * (lane & 3);
            const float bj0 = bias[j], bj1 = bias[j + 1];
            float v00 = acc[mt][nt][0] + bj0;
            float v01 = acc[mt][nt][1] + bj1;
            float v10 = acc[mt][nt][2] + bj0;
            float v11 = acc[mt][nt][3] + bj1;

            if (MODE == 1) {
                float2 lo = {v00, v01}, hi = {v10, v11};
                *(float2*)&Out[(size_t)r_lo * H_DIM + j]       = lo;
                *(float2*)&Out[(size_t)(r_lo + 8) * H_DIM + j] = hi;
            } else {
                const int s = r_lo & 2047;
                const int d = j & 127;
                if (part < 2) {
                    const float sc = part ? 1.0f : kRSqrtHD;
                    float* dst = (part ? g_kT : g_qT)
                               + ((size_t)(b * NHEAD + head) * HDIM) * (size_t)S_LEN;
                    dst[(size_t)d       * S_LEN + s]     = v00 * sc;
                    dst[(size_t)(d + 1) * S_LEN + s]     = v01 * sc;
                    dst[(size_t)d       * S_LEN + s + 8] = v10 * sc;
                    dst[(size_t)(d + 1) * S_LEN + s + 8] = v11 * sc;
                } else {
                    float* dst = g_v + ((size_t)(b * NHEAD + head) * S_LEN) * HDIM;
                    float2 lo = {v00, v01}, hi = {v10, v11};
                    *(float2*)&dst[(size_t)s * HDIM + d]       = lo;
                    *(float2*)&dst[(size_t)(s + 8) * HDIM + d] = hi;
                }
            }
        }
    }
}

// ---------------------------------------------------------------------------
// Causal flash attention (fp32) — unchanged from passing Round 8 version.
// ---------------------------------------------------------------------------
__global__ void __launch_bounds__(256) flash_attn()
{
    extern __shared__ float sm[];
    float* Qs = sm;             // 128*128
    float* KP = sm + 16384;     // 128*128
    float* Vs = sm + 32768;     // 128*128

    const int tid = threadIdx.x;
    const int tx = tid & 15;
    const int ty = tid >> 4;
    const int qb = (int)(gridDim.x - 1) - (int)blockIdx.x;  // longest blocks first
    const int bh = blockIdx.y;

    const float* qT = g_qT + (size_t)bh * HDIM * S_LEN;
    const float* kT = g_kT + (size_t)bh * HDIM * S_LEN;
    const float* vp = g_v  + (size_t)bh * S_LEN * HDIM;

#pragma unroll
    for (int i = 0; i < 16; i++) {
        int idx = tid + i * 256;
        int d = idx >> 5;
        int m4 = (idx & 31) << 2;
        *(float4*)&Qs[d * 128 + m4] =
            *(const float4*)&qT[(size_t)d * S_LEN + qb * 128 + m4];
    }

    float o[8][8];
    float Mr[8], Lr[8];
#pragma unroll
    for (int i = 0; i < 8; i++) {
        Mr[i] = -1e30f;
        Lr[i] = 0.0f;
#pragma unroll
        for (int j = 0; j < 8; j++) o[i][j] = 0.0f;
    }

    int ridx[8], jidx[8];
#pragma unroll
    for (int i = 0; i < 8; i++) ridx[i] = (i < 4) ? (ty * 4 + i) : (64 + ty * 4 + (i - 4));
#pragma unroll
    for (int j = 0; j < 8; j++) jidx[j] = (j < 4) ? (tx * 4 + j) : (64 + tx * 4 + (j - 4));

    for (int kb = 0; kb <= qb; kb++) {
#pragma unroll
        for (int i = 0; i < 16; i++) {
            int idx = tid + i * 256;
            int r = idx >> 5;
            int c4 = (idx & 31) << 2;
            *(float4*)&KP[r * 128 + c4] =
                *(const float4*)&kT[(size_t)r * S_LEN + kb * 128 + c4];
            *(float4*)&Vs[r * 128 + c4] =
                *(const float4*)&vp[(size_t)(kb * 128 + r) * HDIM + c4];
        }
        __syncthreads();

        float s[8][8];
#pragma unroll
        for (int i = 0; i < 8; i++)
#pragma unroll
            for (int j = 0; j < 8; j++) s[i][j] = 0.0f;

#pragma unroll 8
        for (int d = 0; d < 128; d++) {
            float4 a0 = *(const float4*)&Qs[d * 128 + ty * 4];
            float4 a1 = *(const float4*)&Qs[d * 128 + 64 + ty * 4];
            float4 b0 = *(const float4*)&KP[d * 128 + tx * 4];
            float4 b1 = *(const float4*)&KP[d * 128 + 64 + tx * 4];
            float am[8] = {a0.x, a0.y, a0.z, a0.w, a1.x, a1.y, a1.z, a1.w};
            float bn[8] = {b0.x, b0.y, b0.z, b0.w, b1.x, b1.y, b1.z, b1.w};
#pragma unroll
            for (int i = 0; i < 8; i++)
#pragma unroll
                for (int j = 0; j < 8; j++)
                    s[i][j] += am[i] * bn[j];
        }
        __syncthreads();

        if (kb == qb) {
#pragma unroll
            for (int i = 0; i < 8; i++)
#pragma unroll
                for (int j = 0; j < 8; j++)
                    if (jidx[j] > ridx[i]) s[i][j] = -1e30f;
        }

#pragma unroll
        for (int i = 0; i < 8; i++) {
            float mx = s[i][0];
#pragma unroll
            for (int j = 1; j < 8; j++) mx = fmaxf(mx, s[i][j]);
            mx = fmaxf(mx, __shfl_xor_sync(0xffffffffu, mx, 8));
            mx = fmaxf(mx, __shfl_xor_sync(0xffffffffu, mx, 4));
            mx = fmaxf(mx, __shfl_xor_sync(0xffffffffu, mx, 2));
            mx = fmaxf(mx, __shfl_xor_sync(0xffffffffu, mx, 1));

            float mnew = fmaxf(Mr[i], mx);
            float corr = __expf(Mr[i] - mnew);
            Mr[i] = mnew;

            float rsum = 0.0f;
#pragma unroll
            for (int j = 0; j < 8; j++) {
                float p = __expf(s[i][j] - mnew);
                s[i][j] = p;
                rsum += p;
            }
            rsum += __shfl_xor_sync(0xffffffffu, rsum, 8);
            rsum += __shfl_xor_sync(0xffffffffu, rsum, 4);
            rsum += __shfl_xor_sync(0xffffffffu, rsum, 2);
            rsum += __shfl_xor_sync(0xffffffffu, rsum, 1);

            Lr[i] = Lr[i] * corr + rsum;
#pragma unroll
            for (int j = 0; j < 8; j++) o[i][j] *= corr;
        }

#pragma unroll
        for (int j = 0; j < 8; j++) {
            int jj = jidx[j];
            int swz = ((jj >> 2) & 7) << 2;
            int c0 = (ty * 4) ^ swz;
            float4 v0 = {s[0][j], s[1][j], s[2][j], s[3][j]};
            float4 v1 = {s[4][j], s[5][j], s[6][j], s[7][j]};
            *(float4*)&KP[jj * 128 + c0]      = v0;
            *(float4*)&KP[jj * 128 + 64 + c0] = v1;
        }
        __syncthreads();

#pragma unroll 4
        for (int j = 0; j < 128; j++) {
            int swz = ((j >> 2) & 7) << 2;
            int c0 = (ty * 4) ^ swz;
            float4 a0 = *(const float4*)&KP[j * 128 + c0];
            float4 a1 = *(const float4*)&KP[j * 128 + 64 + c0];
            float4 b0 = *(const float4*)&Vs[j * 128 + tx * 4];
            float4 b1 = *(const float4*)&Vs[j * 128 + 64 + tx * 4];
            float am[8] = {a0.x, a0.y, a0.z, a0.w, a1.x, a1.y, a1.z, a1.w};
            float bn[8] = {b0.x, b0.y, b0.z, b0.w, b1.x, b1.y, b1.z, b1.w};
#pragma unroll
            for (int i = 0; i < 8; i++)
#pragma unroll
                for (int jn = 0; jn < 8; jn++)
                    o[i][jn] += am[i] * bn[jn];
        }
        __syncthreads();
    }

    const int b = bh >> 4;
    const int n = bh & 15;
#pragma unroll
    for (int i = 0; i < 8; i++) {
        float inv = 1.0f / Lr[i];
        int srow = qb * 128 + ridx[i];
        float* dst = g_ctx + ((size_t)b * S_LEN + srow) * H_DIM + n * HDIM;
#pragma unroll
        for (int g = 0; g < 2; g++) {
            int c0 = g * 64 + tx * 4;
            float4 vv;
            vv.x = o[i][g * 4 + 0] * inv;
            vv.y = o[i][g * 4 + 1] * inv;
            vv.z = o[i][g * 4 + 2] * inv;
            vv.w = o[i][g * 4 + 3] * inv;
            *(float4*)&dst[c0] = vv;
        }
    }
}

// ---------------------------------------------------------------------------
extern "C" void kernel_launch(void* const* d_in, const int* in_sizes, int n_in,
                              void* d_out, int out_size)
{
    (void)in_sizes; (void)n_in; (void)out_size;
    const float* hidden  = (const float*)d_in[0];
    // d_in[1] = ltor_mask (causal tril) — structure exploited directly
    const float* w_qkv   = (const float*)d_in[2];
    const float* b_qkv   = (const float*)d_in[3];
    const float* w_dense = (const float*)d_in[4];
    const float* b_dense = (const float*)d_in[5];
    float* out = (float*)d_out;

    const int GEMM_SMEM = 65536;
    cudaFuncSetAttribute(gemm_mma<0>, cudaFuncAttributeMaxDynamicSharedMemorySize, GEMM_SMEM);
    cudaFuncSetAttribute(gemm_mma<1>, cudaFuncAttributeMaxDynamicSharedMemorySize, GEMM_SMEM);
    cudaFuncSetAttribute(flash_attn,  cudaFuncAttributeMaxDynamicSharedMemorySize, 196608);

    // 1) QKV: [4096,2048] @ [6144,2048]^T, tiles 128x128
    gemm_mma<0><<<dim3(48, 32), 256, GEMM_SMEM>>>(hidden, w_qkv, b_qkv, nullptr);

    // 2) Causal flash attention over 32 (b,head) pairs x 16 q-blocks
    flash_attn<<<dim3(16, 32), 256, 196608>>>();

    // 3) Dense: [4096,2048] @ [2048,2048]^T
    gemm_mma<1><<<dim3(16, 32), 256, GEMM_SMEM>>>(nullptr, w_dense, b_dense, out);
}

// round 15
// speedup vs baseline: 2.2527x; 1.3552x over previous
#include <cuda_runtime.h>
#include <cstdint>
#include <cstddef>

// Problem constants (B=2, S=2048, H=2048, N=16 heads, HN=128)
#define S_LEN 2048
#define H_DIM 2048
#define NHEAD 16
#define HDIM  128
static __device__ __constant__ float kRSqrtHD = 0.08838834764831845f; // 1/sqrt(128)

// Scratch (device globals — allowed; no runtime allocation)
__device__ float g_q  [32u * 2048u * 128u];   // [b*16+n][s][d]   32 MB (pre-scaled)
__device__ float g_k  [32u * 2048u * 128u];   // [b*16+n][s][d]   32 MB
__device__ float g_vT [32u * 128u * 2048u];   // [b*16+n][d][s]   32 MB
__device__ float g_ctx[2u * 2048u * 2048u];   // [b][s][h]        32 MB

// ---------------------------------------------------------------------------
// Helpers (arch-neutral mma.sync/ldmatrix; no tcgen05 on plain sm_103 target)
// ---------------------------------------------------------------------------
__device__ __forceinline__ uint32_t smem_u32(const void* p) {
    uint32_t a;
    asm("{ .reg .u64 t; cvta.to.shared.u64 t, %1; cvt.u32.u64 %0, t; }"
        : "=r"(a) : "l"(p));
    return a;
}
__device__ __forceinline__ uint32_t f2tf32(float f) {
    uint32_t u;
    asm("cvt.rna.tf32.f32 %0, %1;" : "=r"(u) : "f"(f));
    return u;
}
#define SWZ(o) ((o) ^ (((o) >> 3) & 0x70))

__device__ __forceinline__ void sts_tf32(uint32_t addr, float4 v) {
    uint32_t x = f2tf32(v.x), y = f2tf32(v.y), z = f2tf32(v.z), w = f2tf32(v.w);
    asm volatile("st.shared.v4.b32 [%0], {%1, %2, %3, %4};"
                 :: "r"(addr), "r"(x), "r"(y), "r"(z), "r"(w) : "memory");
}
__device__ __forceinline__ void sts_tf32x2(uint32_t addr, float a, float b) {
    uint32_t x = f2tf32(a), y = f2tf32(b);
    asm volatile("st.shared.v2.b32 [%0], {%1, %2};"
                 :: "r"(addr), "r"(x), "r"(y) : "memory");
}

__device__ __forceinline__ void ldsm_x4(uint32_t* r, uint32_t addr) {
    asm volatile("ldmatrix.sync.aligned.m8n8.x4.shared.b16 {%0,%1,%2,%3}, [%4];"
                 : "=r"(r[0]), "=r"(r[1]), "=r"(r[2]), "=r"(r[3])
                 : "r"(addr));
}

__device__ __forceinline__ void mma_tf32(float* c, const uint32_t* a, const uint32_t* b) {
    asm volatile(
        "mma.sync.aligned.m16n8k8.row.col.f32.tf32.tf32.f32 "
        "{%0,%1,%2,%3}, {%4,%5,%6,%7}, {%8,%9}, {%0,%1,%2,%3};"
        : "+f"(c[0]), "+f"(c[1]), "+f"(c[2]), "+f"(c[3])
        : "r"(a[0]), "r"(a[1]), "r"(a[2]), "r"(a[3]),
          "r"(b[0]), "r"(b[1]));
}

// ---------------------------------------------------------------------------
// tf32 mma.sync GEMM: C[M,*] = A[M,2048] @ W[Ncols,2048]^T + bias
// CTA 128x128, K-chunk 32, double-buffered SW128 smem, 8 warps (2x4),
// warp tile 64x32 (4x4 m16n8k8 tiles), fp32 register accumulators.
// MODE 0: QKV epilogue (q,k row-major into g_q/g_k; v transposed into g_vT)
// MODE 1: dense epilogue (A is g_ctx; row-major store to Out)
// ---------------------------------------------------------------------------
template <int MODE>
__global__ void __launch_bounds__(256) gemm_mma(
    const float* __restrict__ Ain,
    const float* __restrict__ W,
    const float* __restrict__ bias,
    float* __restrict__ Out)
{
    constexpr int K = 2048, CK = 32, NC = K / CK;  // 64 chunks
    extern __shared__ char dynsm[];
    const uint32_t sbase = smem_u32(dynsm);
    // layout: A0 @0 (16K) | B0 @16K | A1 @32K | B1 @48K

    const int tid  = threadIdx.x;
    const int lane = tid & 31;
    const int wid  = tid >> 5;
    const int wm   = wid >> 2;   // 0..1
    const int wn   = wid & 3;    // 0..3
    const int rowBase = blockIdx.y * 128;
    const int colBase = blockIdx.x * 128;
    const float* Aeff = (MODE == 1) ? (const float*)g_ctx : Ain;

    // ---- loader mapping: 2 threads per row, 16 floats (4 x float4) each ----
    const int lrow = tid >> 1;                 // 0..127
    const int lcol = (tid & 1) * 16;           // float offset
    const float* aP = Aeff + (size_t)(rowBase + lrow) * K + lcol;
    const float* bP = W    + (size_t)(colBase + lrow) * K + lcol;
    uint32_t stoff[4];
#pragma unroll
    for (int g = 0; g < 4; g++)
        stoff[g] = SWZ((uint32_t)lrow * 128u + (uint32_t)(lcol + 4 * g) * 4u);

    // ---- compute-lane ldmatrix constants ----
    const int xorv  = lane & 7;
    const int aRow  = ((lane >> 3) & 1) * 8 + (lane & 7); // + wm*64 + mt*16
    const int aGoff = lane >> 4;                          // 0/1
    const int bRow  = (lane >> 4) * 8 + (lane & 7);       // + wn*32 + np*16
    const int bGoff = (lane >> 3) & 1;                    // 0/1

    float acc[4][4][4];
#pragma unroll
    for (int mt = 0; mt < 4; mt++)
#pragma unroll
        for (int nt = 0; nt < 4; nt++)
#pragma unroll
            for (int e = 0; e < 4; e++) acc[mt][nt][e] = 0.0f;

    // prologue: prefetch chunk 0
    float4 ra[4], rb[4];
#pragma unroll
    for (int g = 0; g < 4; g++) {
        ra[g] = *(const float4*)(aP + 4 * g);
        rb[g] = *(const float4*)(bP + 4 * g);
    }

    for (int c = 0; c < NC; c++) {
        const uint32_t Ab = sbase + (uint32_t)(c & 1) * 32768u;
        const uint32_t Bb = Ab + 16384u;

        // store chunk c (cvt.rna to tf32)
#pragma unroll
        for (int g = 0; g < 4; g++) {
            sts_tf32(Ab + stoff[g], ra[g]);
            sts_tf32(Bb + stoff[g], rb[g]);
        }
        __syncthreads();

        // prefetch chunk c+1
        if (c + 1 < NC) {
            const float* ap2 = aP + (size_t)(c + 1) * CK;
            const float* bp2 = bP + (size_t)(c + 1) * CK;
#pragma unroll
            for (int g = 0; g < 4; g++) {
                ra[g] = *(const float4*)(ap2 + 4 * g);
                rb[g] = *(const float4*)(bp2 + 4 * g);
            }
        }

        // compute chunk c
        const uint32_t aBase = Ab + (uint32_t)(wm * 64 + aRow) * 128u;
        const uint32_t bBase = Bb + (uint32_t)(wn * 32 + bRow) * 128u;
#pragma unroll
        for (int ks = 0; ks < 4; ks++) {
            uint32_t afr[4][4], bfr[2][4];
            const uint32_t gA = (uint32_t)(((ks * 2 + aGoff) ^ xorv) * 16);
            const uint32_t gB = (uint32_t)(((ks * 2 + bGoff) ^ xorv) * 16);
#pragma unroll
            for (int mt = 0; mt < 4; mt++)
                ldsm_x4(afr[mt], aBase + (uint32_t)mt * 2048u + gA);
#pragma unroll
            for (int np = 0; np < 2; np++)
                ldsm_x4(bfr[np], bBase + (uint32_t)np * 2048u + gB);
#pragma unroll
            for (int mt = 0; mt < 4; mt++)
#pragma unroll
                for (int nt = 0; nt < 4; nt++)
                    mma_tf32(acc[mt][nt], afr[mt], &bfr[nt >> 1][(nt & 1) * 2]);
        }
        __syncthreads();
    }

    // ---------------- epilogue ----------------
    const int part = colBase >> 11;            // MODE 0: 0=q 1=k 2=v
    const int head = (colBase & 2047) >> 7;
    const int b    = rowBase >> 11;

#pragma unroll
    for (int mt = 0; mt < 4; mt++) {
        const int r_lo = rowBase + wm * 64 + mt * 16 + (lane >> 2);
#pragma unroll
        for (int nt = 0; nt < 4; nt++) {
            const int j = colBase + wn * 32 + nt * 8 + 2 * (lane & 3);
            const float bj0 = bias[j], bj1 = bias[j + 1];
            float v00 = acc[mt][nt][0] + bj0;
            float v01 = acc[mt][nt][1] + bj1;
            float v10 = acc[mt][nt][2] + bj0;
            float v11 = acc[mt][nt][3] + bj1;

            if (MODE == 1) {
                float2 lo = {v00, v01}, hi = {v10, v11};
                *(float2*)&Out[(size_t)r_lo * H_DIM + j]       = lo;
                *(float2*)&Out[(size_t)(r_lo + 8) * H_DIM + j] = hi;
            } else {
                const int s = r_lo & 2047;
                const int d = j & 127;
                if (part < 2) {
                    // q,k: row-major [s][d]
                    const float sc = part ? 1.0f : kRSqrtHD;
                    float* dst = (part ? g_k : g_q)
                               + ((size_t)(b * NHEAD + head) * S_LEN) * HDIM;
                    float2 lo = {v00 * sc, v01 * sc}, hi = {v10 * sc, v11 * sc};
                    *(float2*)&dst[(size_t)s * HDIM + d]       = lo;
                    *(float2*)&dst[(size_t)(s + 8) * HDIM + d] = hi;
                } else {
                    // v: transposed [d][s]
                    float* dst = g_vT + ((size_t)(b * NHEAD + head) * HDIM) * (size_t)S_LEN;
                    dst[(size_t)d       * S_LEN + s]     = v00;
                    dst[(size_t)(d + 1) * S_LEN + s]     = v01;
                    dst[(size_t)d       * S_LEN + s + 8] = v10;
                    dst[(size_t)(d + 1) * S_LEN + s + 8] = v11;
                }
            }
        }
    }
}

// ---------------------------------------------------------------------------
// Causal flash attention with tf32 mma.sync for S=QK^T and O+=PV.
// CTA: 128 q-rows x d=128, tiles of 128 k-cols. 8 warps (2x4), warp 64x32.
// Smem: Qs 64KB | K-tile (reused as P) 64KB | V 64KB | stats 4KB = 196.6KB+4KB
// Row softmax == reference (global-max shift cancels; masked exp -> 0).
// ---------------------------------------------------------------------------
__global__ void __launch_bounds__(256) flash_mma()
{
    extern __shared__ char dynsm[];
    const uint32_t QsB  = smem_u32(dynsm);
    const uint32_t KPsB = QsB + 65536u;
    const uint32_t VsB  = QsB + 131072u;
    float* pmax = (float*)(dynsm + 196608);          // [128][4]
    float* psum = (float*)(dynsm + 196608 + 2048);   // [128][4]

    const int tid  = threadIdx.x;
    const int lane = tid & 31;
    const int wid  = tid >> 5;
    const int wm   = wid >> 2;   // 0..1
    const int wn   = wid & 3;    // 0..3
    const int qb   = (int)(gridDim.x - 1) - (int)blockIdx.x;  // longest first
    const int bh   = blockIdx.y;

    const int xorv  = lane & 7;
    const int aRow  = ((lane >> 3) & 1) * 8 + (lane & 7);
    const int aGoff = lane >> 4;
    const int bRow  = (lane >> 4) * 8 + (lane & 7);
    const int bGoff = (lane >> 3) & 1;

    const int lrow = tid >> 1;
    const int lcol = (tid & 1) * 16;
    uint32_t stoff[4];
#pragma unroll
    for (int g = 0; g < 4; g++)
        stoff[g] = SWZ((uint32_t)lrow * 128u + (uint32_t)(lcol + 4 * g) * 4u);

    const float* gq = g_q  + (size_t)bh * S_LEN * HDIM + (size_t)qb * 128 * HDIM;
    const float* gk = g_k  + (size_t)bh * S_LEN * HDIM;
    const float* gv = g_vT + (size_t)bh * HDIM * S_LEN;

    // ---- load Q tile (tf32) into Qs: 4 sub-tiles [128][32] ----
#pragma unroll
    for (int ksub = 0; ksub < 4; ksub++)
#pragma unroll
        for (int g = 0; g < 4; g++) {
            float4 v = *(const float4*)&gq[(size_t)lrow * HDIM + ksub * 32 + lcol + 4 * g];
            sts_tf32(QsB + (uint32_t)ksub * 16384u + stoff[g], v);
        }

    float o[4][4][4];
    float Mr[8], Lr[8];   // idx = mt*2 + h
#pragma unroll
    for (int i = 0; i < 8; i++) { Mr[i] = -1e30f; Lr[i] = 0.0f; }
#pragma unroll
    for (int mt = 0; mt < 4; mt++)
#pragma unroll
        for (int nt = 0; nt < 4; nt++)
#pragma unroll
            for (int e = 0; e < 4; e++) o[mt][nt][e] = 0.0f;

    for (int kb = 0; kb <= qb; kb++) {
        // ---- load K, V tiles ----
        const float* gkt = gk + (size_t)kb * 128 * HDIM;
        const float* gvt = gv + (size_t)kb * 128;
#pragma unroll
        for (int ksub = 0; ksub < 4; ksub++)
#pragma unroll
            for (int g = 0; g < 4; g++) {
                float4 kv = *(const float4*)&gkt[(size_t)lrow * HDIM + ksub * 32 + lcol + 4 * g];
                float4 vv = *(const float4*)&gvt[(size_t)lrow * S_LEN + ksub * 32 + lcol + 4 * g];
                sts_tf32(KPsB + (uint32_t)ksub * 16384u + stoff[g], kv);
                sts_tf32(VsB  + (uint32_t)ksub * 16384u + stoff[g], vv);
            }
        __syncthreads();

        // ---- S = Q K^T ----
        float sAcc[4][4][4];
#pragma unroll
        for (int mt = 0; mt < 4; mt++)
#pragma unroll
            for (int nt = 0; nt < 4; nt++)
#pragma unroll
                for (int e = 0; e < 4; e++) sAcc[mt][nt][e] = 0.0f;

#pragma unroll
        for (int ks = 0; ks < 16; ks++) {
            const int ksub = ks >> 2, k2 = ks & 3;
            uint32_t afr[4][4], bfr[2][4];
            const uint32_t gA = (uint32_t)(((k2 * 2 + aGoff) ^ xorv) * 16);
            const uint32_t gB = (uint32_t)(((k2 * 2 + bGoff) ^ xorv) * 16);
            const uint32_t aB = QsB  + (uint32_t)ksub * 16384u + (uint32_t)(wm * 64 + aRow) * 128u;
            const uint32_t bB = KPsB + (uint32_t)ksub * 16384u + (uint32_t)(wn * 32 + bRow) * 128u;
#pragma unroll
            for (int mt = 0; mt < 4; mt++)
                ldsm_x4(afr[mt], aB + (uint32_t)mt * 2048u + gA);
#pragma unroll
            for (int np = 0; np < 2; np++)
                ldsm_x4(bfr[np], bB + (uint32_t)np * 2048u + gB);
#pragma unroll
            for (int mt = 0; mt < 4; mt++)
#pragma unroll
                for (int nt = 0; nt < 4; nt++)
                    mma_tf32(sAcc[mt][nt], afr[mt], &bfr[nt >> 1][(nt & 1) * 2]);
        }

        // ---- causal mask on diagonal tile ----
        if (kb == qb) {
#pragma unroll
            for (int mt = 0; mt < 4; mt++)
#pragma unroll
                for (int h = 0; h < 2; h++) {
                    const int lr = wm * 64 + mt * 16 + (lane >> 2) + h * 8;
#pragma unroll
                    for (int nt = 0; nt < 4; nt++) {
                        const int lc = wn * 32 + nt * 8 + 2 * (lane & 3);
                        if (lc     > lr) sAcc[mt][nt][h * 2 + 0] = -1e30f;
                        if (lc + 1 > lr) sAcc[mt][nt][h * 2 + 1] = -1e30f;
                    }
                }
        }

        // ---- stats pass 1: warp-partial row max -> smem ----
#pragma unroll
        for (int mt = 0; mt < 4; mt++)
#pragma unroll
            for (int h = 0; h < 2; h++) {
                float m = -1e30f;
#pragma unroll
                for (int nt = 0; nt < 4; nt++)
                    m = fmaxf(m, fmaxf(sAcc[mt][nt][h * 2], sAcc[mt][nt][h * 2 + 1]));
                m = fmaxf(m, __shfl_xor_sync(0xffffffffu, m, 1));
                m = fmaxf(m, __shfl_xor_sync(0xffffffffu, m, 2));
                if ((lane & 3) == 0)
                    pmax[(wm * 64 + mt * 16 + (lane >> 2) + h * 8) * 4 + wn] = m;
            }
        __syncthreads();   // also: all S-mma ldsm done -> K buffer reusable as P

        // ---- stats pass 2: exp, partial sums, rescale O, store P ----
#pragma unroll
        for (int mt = 0; mt < 4; mt++)
#pragma unroll
            for (int h = 0; h < 2; h++) {
                const int idx = mt * 2 + h;
                const int row = wm * 64 + mt * 16 + (lane >> 2) + h * 8;
                float4 pm = *(float4*)&pmax[row * 4];
                float mnew = fmaxf(fmaxf(pm.x, pm.y), fmaxf(pm.z, pm.w));
                mnew = fmaxf(mnew, Mr[idx]);
                const float corr = __expf(Mr[idx] - mnew);
                Mr[idx] = mnew;
                float rs = 0.0f;
#pragma unroll
                for (int nt = 0; nt < 4; nt++) {
                    float p0 = __expf(sAcc[mt][nt][h * 2]     - mnew);
                    float p1 = __expf(sAcc[mt][nt][h * 2 + 1] - mnew);
                    sAcc[mt][nt][h * 2]     = p0;
                    sAcc[mt][nt][h * 2 + 1] = p1;
                    rs += p0 + p1;
                }
                rs += __shfl_xor_sync(0xffffffffu, rs, 1);
                rs += __shfl_xor_sync(0xffffffffu, rs, 2);
                if ((lane & 3) == 0) psum[row * 4 + wn] = rs;
                Lr[idx] *= corr;
#pragma unroll
                for (int nt = 0; nt < 4; nt++) {
                    o[mt][nt][h * 2]     *= corr;
                    o[mt][nt][h * 2 + 1] *= corr;
                }
                // store P rows (tf32) into KPs buffer: sub-tile = wn
#pragma unroll
                for (int nt = 0; nt < 4; nt++) {
                    const uint32_t col4 = (uint32_t)(nt * 8 + 2 * (lane & 3)) * 4u;
                    const uint32_t addr = KPsB + (uint32_t)wn * 16384u
                                        + SWZ((uint32_t)row * 128u + col4);
                    sts_tf32x2(addr, sAcc[mt][nt][h * 2], sAcc[mt][nt][h * 2 + 1]);
                }
            }
        __syncthreads();

        // ---- Lr += global row sum ----
#pragma unroll
        for (int mt = 0; mt < 4; mt++)
#pragma unroll
            for (int h = 0; h < 2; h++) {
                const int row = wm * 64 + mt * 16 + (lane >> 2) + h * 8;
                float4 ps = *(float4*)&psum[row * 4];
                Lr[mt * 2 + h] += (ps.x + ps.y) + (ps.z + ps.w);
            }

        // ---- O += P V ----
#pragma unroll
        for (int ks = 0; ks < 16; ks++) {
            const int ksub = ks >> 2, k2 = ks & 3;
            uint32_t afr[4][4], bfr[2][4];
            const uint32_t gA = (uint32_t)(((k2 * 2 + aGoff) ^ xorv) * 16);
            const uint32_t gB = (uint32_t)(((k2 * 2 + bGoff) ^ xorv) * 16);
            const uint32_t aB = KPsB + (uint32_t)ksub * 16384u + (uint32_t)(wm * 64 + aRow) * 128u;
            const uint32_t bB = VsB  + (uint32_t)ksub * 16384u + (uint32_t)(wn * 32 + bRow) * 128u;
#pragma unroll
            for (int mt = 0; mt < 4; mt++)
                ldsm_x4(afr[mt], aB + (uint32_t)mt * 2048u + gA);
#pragma unroll
            for (int np = 0; np < 2; np++)
                ldsm_x4(bfr[np], bB + (uint32_t)np * 2048u + gB);
#pragma unroll
            for (int mt = 0; mt < 4; mt++)
#pragma unroll
                for (int nt = 0; nt < 4; nt++)
                    mma_tf32(o[mt][nt], afr[mt], &bfr[nt >> 1][(nt & 1) * 2]);
        }
        __syncthreads();   // P/V buffers free for next kb
    }

    // ---- normalize and store ctx [b][s][h] ----
    const int b = bh >> 4;
    const int n = bh & 15;
#pragma unroll
    for (int mt = 0; mt < 4; mt++)
#pragma unroll
        for (int h = 0; h < 2; h++) {
            const int row = qb * 128 + wm * 64 + mt * 16 + (lane >> 2) + h * 8;
            const float inv = 1.0f / Lr[mt * 2 + h];
            float* dst = g_ctx + ((size_t)b * S_LEN + row) * H_DIM + n * HDIM;
#pragma unroll
            for (int nt = 0; nt < 4; nt++) {
                const int col = wn * 32 + nt * 8 + 2 * (lane & 3);
                float2 v = {o[mt][nt][h * 2] * inv, o[mt][nt][h * 2 + 1] * inv};
                *(float2*)&dst[col] = v;
            }
        }
}

// ---------------------------------------------------------------------------
extern "C" void kernel_launch(void* const* d_in, const int* in_sizes, int n_in,
                              void* d_out, int out_size)
{
    (void)in_sizes; (void)n_in; (void)out_size;
    const float* hidden  = (const float*)d_in[0];
    // d_in[1] = ltor_mask (causal tril) — structure exploited directly
    const float* w_qkv   = (const float*)d_in[2];
    const float* b_qkv   = (const float*)d_in[3];
    const float* w_dense = (const float*)d_in[4];
    const float* b_dense = (const float*)d_in[5];
    float* out = (float*)d_out;

    const int GEMM_SMEM  = 65536;
    const int FLASH_SMEM = 196608 + 4096;
    cudaFuncSetAttribute(gemm_mma<0>, cudaFuncAttributeMaxDynamicSharedMemorySize, GEMM_SMEM);
    cudaFuncSetAttribute(gemm_mma<1>, cudaFuncAttributeMaxDynamicSharedMemorySize, GEMM_SMEM);
    cudaFuncSetAttribute(flash_mma,   cudaFuncAttributeMaxDynamicSharedMemorySize, FLASH_SMEM);

    // 1) QKV: [4096,2048] @ [6144,2048]^T, tiles 128x128
    gemm_mma<0><<<dim3(48, 32), 256, GEMM_SMEM>>>(hidden, w_qkv, b_qkv, nullptr);

    // 2) Causal flash attention (tensor-core) over 32 (b,head) pairs x 16 q-blocks
    flash_mma<<<dim3(16, 32), 256, FLASH_SMEM>>>();

    // 3) Dense: [4096,2048] @ [2048,2048]^T
    gemm_mma<1><<<dim3(16, 32), 256, GEMM_SMEM>>>(nullptr, w_dense, b_dense, out);
}

// round 16
// speedup vs baseline: 2.8204x; 1.2520x over previous
#include <cuda_runtime.h>
#include <cstdint>
#include <cstddef>

// Problem constants (B=2, S=2048, H=2048, N=16 heads, HN=128)
#define S_LEN 2048
#define H_DIM 2048
#define NHEAD 16
#define HDIM  128
static __device__ __constant__ float kRSqrtHD = 0.08838834764831845f; // 1/sqrt(128)

// Scratch (device globals — allowed; no runtime allocation)
__device__ float g_q  [32u * 2048u * 128u];   // [b*16+n][s][d]  tf32-rounded, pre-scaled
__device__ float g_k  [32u * 2048u * 128u];   // [b*16+n][s][d]  tf32-rounded
__device__ float g_vT [32u * 128u * 2048u];   // [b*16+n][d][s]  tf32-rounded
__device__ float g_ctx[2u * 2048u * 2048u];   // [b][s][h]       tf32-rounded
__device__ float g_hid[2u * 2048u * 2048u];   // tf32-rounded hidden
__device__ float g_wq [3u * 2048u * 2048u];   // tf32-rounded w_qkv
__device__ float g_wd [2048u * 2048u];        // tf32-rounded w_dense

// ---------------------------------------------------------------------------
// Helpers (arch-neutral mma.sync/ldmatrix/cp.async; no tcgen05 on sm_103)
// ---------------------------------------------------------------------------
__device__ __forceinline__ uint32_t smem_u32(const void* p) {
    uint32_t a;
    asm("{ .reg .u64 t; cvta.to.shared.u64 t, %1; cvt.u32.u64 %0, t; }"
        : "=r"(a) : "l"(p));
    return a;
}
__device__ __forceinline__ uint32_t f2tf32(float f) {
    uint32_t u;
    asm("cvt.rna.tf32.f32 %0, %1;" : "=r"(u) : "f"(f));
    return u;
}
__device__ __forceinline__ float rtf(float f) { return __uint_as_float(f2tf32(f)); }
#define SWZ(o) ((o) ^ (((o) >> 3) & 0x70))

__device__ __forceinline__ void cp16(uint32_t dst, const void* src) {
    asm volatile("cp.async.cg.shared.global [%0], [%1], 16;"
                 :: "r"(dst), "l"(src) : "memory");
}
#define CP_COMMIT() asm volatile("cp.async.commit_group;" ::: "memory")
#define CP_WAIT(n)  asm volatile("cp.async.wait_group %0;" :: "n"(n) : "memory")

__device__ __forceinline__ void sts_tf32x2(uint32_t addr, float a, float b) {
    uint32_t x = f2tf32(a), y = f2tf32(b);
    asm volatile("st.shared.v2.b32 [%0], {%1, %2};"
                 :: "r"(addr), "r"(x), "r"(y) : "memory");
}

__device__ __forceinline__ void ldsm_x4(uint32_t* r, uint32_t addr) {
    asm volatile("ldmatrix.sync.aligned.m8n8.x4.shared.b16 {%0,%1,%2,%3}, [%4];"
                 : "=r"(r[0]), "=r"(r[1]), "=r"(r[2]), "=r"(r[3])
                 : "r"(addr));
}

__device__ __forceinline__ void mma_tf32(float* c, const uint32_t* a, const uint32_t* b) {
    asm volatile(
        "mma.sync.aligned.m16n8k8.row.col.f32.tf32.tf32.f32 "
        "{%0,%1,%2,%3}, {%4,%5,%6,%7}, {%8,%9}, {%0,%1,%2,%3};"
        : "+f"(c[0]), "+f"(c[1]), "+f"(c[2]), "+f"(c[3])
        : "r"(a[0]), "r"(a[1]), "r"(a[2]), "r"(a[3]),
          "r"(b[0]), "r"(b[1]));
}

// ---------------------------------------------------------------------------
// Pre-pass: tf32-round fp32 arrays in gmem (values become exactly tf32-
// representable, so cp.async raw copies are numerically identical to cvt.rna)
// ---------------------------------------------------------------------------
__global__ void round4(const float* __restrict__ src, float* __restrict__ dst, int n4)
{
    int i = blockIdx.x * blockDim.x + threadIdx.x;
    if (i < n4) {
        float4 v = ((const float4*)src)[i];
        v.x = rtf(v.x); v.y = rtf(v.y); v.z = rtf(v.z); v.w = rtf(v.w);
        ((float4*)dst)[i] = v;
    }
}

// ---------------------------------------------------------------------------
// tf32 mma.sync GEMM with 3-stage cp.async pipeline.
// C[M,*] = A[M,2048] @ W[Ncols,2048]^T + bias. CTA 128x128, K-chunk 32,
// 8 warps (2x4), warp tile 64x32, fp32 register accumulators, 2 CTAs/SM.
// Inputs MUST be pre-rounded to tf32.
// MODE 0: QKV epilogue (q,k row-major into g_q/g_k; v transposed into g_vT)
// MODE 1: dense epilogue (A is g_ctx; row-major fp32 store to Out)
// ---------------------------------------------------------------------------
template <int MODE>
__global__ void __launch_bounds__(256, 2) gemm_mma(
    const float* __restrict__ Ain,
    const float* __restrict__ W,
    const float* __restrict__ bias,
    float* __restrict__ Out)
{
    constexpr int K = 2048, CK = 32, NC = K / CK, ST = 3;
    extern __shared__ char dynsm[];
    const uint32_t sbase = smem_u32(dynsm);
    // stage s: A @ s*32768, B @ s*32768+16384

    const int tid  = threadIdx.x;
    const int lane = tid & 31;
    const int wid  = tid >> 5;
    const int wm   = wid >> 2;   // 0..1
    const int wn   = wid & 3;    // 0..3
    const int rowBase = blockIdx.y * 128;
    const int colBase = blockIdx.x * 128;
    const float* Aeff = (MODE == 1) ? (const float*)g_ctx : Ain;

    // loader mapping: 2 threads per row, 16 floats (4 x cp.async16) each
    const int lrow = tid >> 1;
    const int lcol = (tid & 1) * 16;
    const float* aP = Aeff + (size_t)(rowBase + lrow) * K + lcol;
    const float* bP = W    + (size_t)(colBase + lrow) * K + lcol;
    uint32_t stoff[4];
#pragma unroll
    for (int g = 0; g < 4; g++)
        stoff[g] = SWZ((uint32_t)lrow * 128u + (uint32_t)(lcol + 4 * g) * 4u);

    // compute-lane ldmatrix constants
    const int xorv  = lane & 7;
    const int aRow  = ((lane >> 3) & 1) * 8 + (lane & 7);
    const int aGoff = lane >> 4;
    const int bRow  = (lane >> 4) * 8 + (lane & 7);
    const int bGoff = (lane >> 3) & 1;

    float acc[4][4][4];
#pragma unroll
    for (int mt = 0; mt < 4; mt++)
#pragma unroll
        for (int nt = 0; nt < 4; nt++)
#pragma unroll
            for (int e = 0; e < 4; e++) acc[mt][nt][e] = 0.0f;

    // ---- cp.async issue for chunk c into stage c%ST ----
    auto issue = [&](int c) {
        const uint32_t Ab = sbase + (uint32_t)(c % ST) * 32768u;
        const float* ap = aP + (size_t)c * CK;
        const float* bp = bP + (size_t)c * CK;
#pragma unroll
        for (int g = 0; g < 4; g++) {
            cp16(Ab + stoff[g], ap + 4 * g);
            cp16(Ab + 16384u + stoff[g], bp + 4 * g);
        }
    };

    issue(0); CP_COMMIT();
    issue(1); CP_COMMIT();
    issue(2); CP_COMMIT();

    for (int c = 0; c < NC; c++) {
        CP_WAIT(2);          // one commit per iteration keeps this exact
        __syncthreads();

        const uint32_t Ab = sbase + (uint32_t)(c % ST) * 32768u;
        const uint32_t aBase = Ab + (uint32_t)(wm * 64 + aRow) * 128u;
        const uint32_t bBase = Ab + 16384u + (uint32_t)(wn * 32 + bRow) * 128u;
#pragma unroll
        for (int ks = 0; ks < 4; ks++) {
            uint32_t afr[4][4], bfr[2][4];
            const uint32_t gA = (uint32_t)(((ks * 2 + aGoff) ^ xorv) * 16);
            const uint32_t gB = (uint32_t)(((ks * 2 + bGoff) ^ xorv) * 16);
#pragma unroll
            for (int mt = 0; mt < 4; mt++)
                ldsm_x4(afr[mt], aBase + (uint32_t)mt * 2048u + gA);
#pragma unroll
            for (int np = 0; np < 2; np++)
                ldsm_x4(bfr[np], bBase + (uint32_t)np * 2048u + gB);
#pragma unroll
            for (int mt = 0; mt < 4; mt++)
#pragma unroll
                for (int nt = 0; nt < 4; nt++)
                    mma_tf32(acc[mt][nt], afr[mt], &bfr[nt >> 1][(nt & 1) * 2]);
        }
        __syncthreads();

        if (c + ST < NC) issue(c + ST);
        CP_COMMIT();
    }

    // ---------------- epilogue ----------------
    const int part = colBase >> 11;            // MODE 0: 0=q 1=k 2=v
    const int head = (colBase & 2047) >> 7;
    const int b    = rowBase >> 11;

#pragma unroll
    for (int mt = 0; mt < 4; mt++) {
        const int r_lo = rowBase + wm * 64 + mt * 16 + (lane >> 2);
#pragma unroll
        for (int nt = 0; nt < 4; nt++) {
            const int j = colBase + wn * 32 + nt * 8 + 2 * (lane & 3);
            const float bj0 = bias[j], bj1 = bias[j + 1];
            float v00 = acc[mt][nt][0] + bj0;
            float v01 = acc[mt][nt][1] + bj1;
            float v10 = acc[mt][nt][2] + bj0;
            float v11 = acc[mt][nt][3] + bj1;

            if (MODE == 1) {
                float2 lo = {v00, v01}, hi = {v10, v11};
                *(float2*)&Out[(size_t)r_lo * H_DIM + j]       = lo;
                *(float2*)&Out[(size_t)(r_lo + 8) * H_DIM + j] = hi;
            } else {
                const int s = r_lo & 2047;
                const int d = j & 127;
                if (part < 2) {
                    // q,k: row-major [s][d], tf32-rounded (flash cp.asyncs these)
                    const float sc = part ? 1.0f : kRSqrtHD;
                    float* dst = (part ? g_k : g_q)
                               + ((size_t)(b * NHEAD + head) * S_LEN) * HDIM;
                    float2 lo = {rtf(v00 * sc), rtf(v01 * sc)};
                    float2 hi = {rtf(v10 * sc), rtf(v11 * sc)};
                    *(float2*)&dst[(size_t)s * HDIM + d]       = lo;
                    *(float2*)&dst[(size_t)(s + 8) * HDIM + d] = hi;
                } else {
                    // v: transposed [d][s], tf32-rounded
                    float* dst = g_vT + ((size_t)(b * NHEAD + head) * HDIM) * (size_t)S_LEN;
                    dst[(size_t)d       * S_LEN + s]     = rtf(v00);
                    dst[(size_t)(d + 1) * S_LEN + s]     = rtf(v01);
                    dst[(size_t)d       * S_LEN + s + 8] = rtf(v10);
                    dst[(size_t)(d + 1) * S_LEN + s + 8] = rtf(v11);
                }
            }
        }
    }
}

// ---------------------------------------------------------------------------
// Causal flash attention with tf32 mma.sync; Q/K/V via cp.async (pre-rounded).
// CTA: 128 q-rows, tiles of 128 k-cols. 8 warps (2x4), warp 64x32.
// Smem: Qs 64KB | K-tile (reused as P) 64KB | V 64KB | stats 4KB
// ---------------------------------------------------------------------------
__global__ void __launch_bounds__(256) flash_mma()
{
    extern __shared__ char dynsm[];
    const uint32_t QsB  = smem_u32(dynsm);
    const uint32_t KPsB = QsB + 65536u;
    const uint32_t VsB  = QsB + 131072u;
    float* pmax = (float*)(dynsm + 196608);          // [128][4]
    float* psum = (float*)(dynsm + 196608 + 2048);   // [128][4]

    const int tid  = threadIdx.x;
    const int lane = tid & 31;
    const int wid  = tid >> 5;
    const int wm   = wid >> 2;
    const int wn   = wid & 3;
    const int qb   = (int)(gridDim.x - 1) - (int)blockIdx.x;  // longest first
    const int bh   = blockIdx.y;

    const int xorv  = lane & 7;
    const int aRow  = ((lane >> 3) & 1) * 8 + (lane & 7);
    const int aGoff = lane >> 4;
    const int bRow  = (lane >> 4) * 8 + (lane & 7);
    const int bGoff = (lane >> 3) & 1;

    const int lrow = tid >> 1;
    const int lcol = (tid & 1) * 16;
    uint32_t stoff[4];
#pragma unroll
    for (int g = 0; g < 4; g++)
        stoff[g] = SWZ((uint32_t)lrow * 128u + (uint32_t)(lcol + 4 * g) * 4u);

    const float* gq = g_q  + (size_t)bh * S_LEN * HDIM + (size_t)qb * 128 * HDIM;
    const float* gk = g_k  + (size_t)bh * S_LEN * HDIM;
    const float* gv = g_vT + (size_t)bh * HDIM * S_LEN;

    // ---- Q tile via cp.async ----
#pragma unroll
    for (int ksub = 0; ksub < 4; ksub++)
#pragma unroll
        for (int g = 0; g < 4; g++)
            cp16(QsB + (uint32_t)ksub * 16384u + stoff[g],
                 &gq[(size_t)lrow * HDIM + ksub * 32 + lcol + 4 * g]);
    CP_COMMIT();

    float o[4][4][4];
    float Mr[8], Lr[8];
#pragma unroll
    for (int i = 0; i < 8; i++) { Mr[i] = -1e30f; Lr[i] = 0.0f; }
#pragma unroll
    for (int mt = 0; mt < 4; mt++)
#pragma unroll
        for (int nt = 0; nt < 4; nt++)
#pragma unroll
            for (int e = 0; e < 4; e++) o[mt][nt][e] = 0.0f;

    for (int kb = 0; kb <= qb; kb++) {
        // ---- K, V tiles via cp.async ----
        const float* gkt = gk + (size_t)kb * 128 * HDIM;
        const float* gvt = gv + (size_t)kb * 128;
#pragma unroll
        for (int ksub = 0; ksub < 4; ksub++)
#pragma unroll
            for (int g = 0; g < 4; g++) {
                cp16(KPsB + (uint32_t)ksub * 16384u + stoff[g],
                     &gkt[(size_t)lrow * HDIM + ksub * 32 + lcol + 4 * g]);
                cp16(VsB + (uint32_t)ksub * 16384u + stoff[g],
                     &gvt[(size_t)lrow * S_LEN + ksub * 32 + lcol + 4 * g]);
            }
        CP_COMMIT();
        CP_WAIT(0);
        __syncthreads();

        // ---- S = Q K^T ----
        float sAcc[4][4][4];
#pragma unroll
        for (int mt = 0; mt < 4; mt++)
#pragma unroll
            for (int nt = 0; nt < 4; nt++)
#pragma unroll
                for (int e = 0; e < 4; e++) sAcc[mt][nt][e] = 0.0f;

#pragma unroll
        for (int ks = 0; ks < 16; ks++) {
            const int ksub = ks >> 2, k2 = ks & 3;
            uint32_t afr[4][4], bfr[2][4];
            const uint32_t gA = (uint32_t)(((k2 * 2 + aGoff) ^ xorv) * 16);
            const uint32_t gB = (uint32_t)(((k2 * 2 + bGoff) ^ xorv) * 16);
            const uint32_t aB = QsB  + (uint32_t)ksub * 16384u + (uint32_t)(wm * 64 + aRow) * 128u;
            const uint32_t bB = KPsB + (uint32_t)ksub * 16384u + (uint32_t)(wn * 32 + bRow) * 128u;
#pragma unroll
            for (int mt = 0; mt < 4; mt++)
                ldsm_x4(afr[mt], aB + (uint32_t)mt * 2048u + gA);
#pragma unroll
            for (int np = 0; np < 2; np++)
                ldsm_x4(bfr[np], bB + (uint32_t)np * 2048u + gB);
#pragma unroll
            for (int mt = 0; mt < 4; mt++)
#pragma unroll
                for (int nt = 0; nt < 4; nt++)
                    mma_tf32(sAcc[mt][nt], afr[mt], &bfr[nt >> 1][(nt & 1) * 2]);
        }

        // ---- causal mask on diagonal tile ----
        if (kb == qb) {
#pragma unroll
            for (int mt = 0; mt < 4; mt++)
#pragma unroll
                for (int h = 0; h < 2; h++) {
                    const int lr = wm * 64 + mt * 16 + (lane >> 2) + h * 8;
#pragma unroll
                    for (int nt = 0; nt < 4; nt++) {
                        const int lc = wn * 32 + nt * 8 + 2 * (lane & 3);
                        if (lc     > lr) sAcc[mt][nt][h * 2 + 0] = -1e30f;
                        if (lc + 1 > lr) sAcc[mt][nt][h * 2 + 1] = -1e30f;
                    }
                }
        }

        // ---- stats pass 1: warp-partial row max -> smem ----
#pragma unroll
        for (int mt = 0; mt < 4; mt++)
#pragma unroll
            for (int h = 0; h < 2; h++) {
                float m = -1e30f;
#pragma unroll
                for (int nt = 0; nt < 4; nt++)
                    m = fmaxf(m, fmaxf(sAcc[mt][nt][h * 2], sAcc[mt][nt][h * 2 + 1]));
                m = fmaxf(m, __shfl_xor_sync(0xffffffffu, m, 1));
                m = fmaxf(m, __shfl_xor_sync(0xffffffffu, m, 2));
                if ((lane & 3) == 0)
                    pmax[(wm * 64 + mt * 16 + (lane >> 2) + h * 8) * 4 + wn] = m;
            }
        __syncthreads();   // all S-mma ldsm done -> K buffer reusable as P

        // ---- stats pass 2: exp, partial sums, rescale O, store P ----
#pragma unroll
        for (int mt = 0; mt < 4; mt++)
#pragma unroll
            for (int h = 0; h < 2; h++) {
                const int idx = mt * 2 + h;
                const int row = wm * 64 + mt * 16 + (lane >> 2) + h * 8;
                float4 pm = *(float4*)&pmax[row * 4];
                float mnew = fmaxf(fmaxf(pm.x, pm.y), fmaxf(pm.z, pm.w));
                mnew = fmaxf(mnew, Mr[idx]);
                const float corr = __expf(Mr[idx] - mnew);
                Mr[idx] = mnew;
                float rs = 0.0f;
#pragma unroll
                for (int nt = 0; nt < 4; nt++) {
                    float p0 = __expf(sAcc[mt][nt][h * 2]     - mnew);
                    float p1 = __expf(sAcc[mt][nt][h * 2 + 1] - mnew);
                    sAcc[mt][nt][h * 2]     = p0;
                    sAcc[mt][nt][h * 2 + 1] = p1;
                    rs += p0 + p1;
                }
                rs += __shfl_xor_sync(0xffffffffu, rs, 1);
                rs += __shfl_xor_sync(0xffffffffu, rs, 2);
                if ((lane & 3) == 0) psum[row * 4 + wn] = rs;
                Lr[idx] *= corr;
#pragma unroll
                for (int nt = 0; nt < 4; nt++) {
                    o[mt][nt][h * 2]     *= corr;
                    o[mt][nt][h * 2 + 1] *= corr;
                }
#pragma unroll
                for (int nt = 0; nt < 4; nt++) {
                    const uint32_t col4 = (uint32_t)(nt * 8 + 2 * (lane & 3)) * 4u;
                    const uint32_t addr = KPsB + (uint32_t)wn * 16384u
                                        + SWZ((uint32_t)row * 128u + col4);
                    sts_tf32x2(addr, sAcc[mt][nt][h * 2], sAcc[mt][nt][h * 2 + 1]);
                }
            }
        __syncthreads();

        // ---- Lr += global row sum ----
#pragma unroll
        for (int mt = 0; mt < 4; mt++)
#pragma unroll
            for (int h = 0; h < 2; h++) {
                const int row = wm * 64 + mt * 16 + (lane >> 2) + h * 8;
                float4 ps = *(float4*)&psum[row * 4];
                Lr[mt * 2 + h] += (ps.x + ps.y) + (ps.z + ps.w);
            }

        // ---- O += P V ----
#pragma unroll
        for (int ks = 0; ks < 16; ks++) {
            const int ksub = ks >> 2, k2 = ks & 3;
            uint32_t afr[4][4], bfr[2][4];
            const uint32_t gA = (uint32_t)(((k2 * 2 + aGoff) ^ xorv) * 16);
            const uint32_t gB = (uint32_t)(((k2 * 2 + bGoff) ^ xorv) * 16);
            const uint32_t aB = KPsB + (uint32_t)ksub * 16384u + (uint32_t)(wm * 64 + aRow) * 128u;
            const uint32_t bB = VsB  + (uint32_t)ksub * 16384u + (uint32_t)(wn * 32 + bRow) * 128u;
#pragma unroll
            for (int mt = 0; mt < 4; mt++)
                ldsm_x4(afr[mt], aB + (uint32_t)mt * 2048u + gA);
#pragma unroll
            for (int np = 0; np < 2; np++)
                ldsm_x4(bfr[np], bB + (uint32_t)np * 2048u + gB);
#pragma unroll
            for (int mt = 0; mt < 4; mt++)
#pragma unroll
                for (int nt = 0; nt < 4; nt++)
                    mma_tf32(o[mt][nt], afr[mt], &bfr[nt >> 1][(nt & 1) * 2]);
        }
        __syncthreads();   // P/V buffers free for next kb
    }

    // ---- normalize and store ctx [b][s][h] (tf32-rounded for dense cp.async) ----
    const int b = bh >> 4;
    const int n = bh & 15;
#pragma unroll
    for (int mt = 0; mt < 4; mt++)
#pragma unroll
        for (int h = 0; h < 2; h++) {
            const int row = qb * 128 + wm * 64 + mt * 16 + (lane >> 2) + h * 8;
            const float inv = 1.0f / Lr[mt * 2 + h];
            float* dst = g_ctx + ((size_t)b * S_LEN + row) * H_DIM + n * HDIM;
#pragma unroll
            for (int nt = 0; nt < 4; nt++) {
                const int col = wn * 32 + nt * 8 + 2 * (lane & 3);
                float2 v = {rtf(o[mt][nt][h * 2] * inv), rtf(o[mt][nt][h * 2 + 1] * inv)};
                *(float2*)&dst[col] = v;
            }
        }
}

// ---------------------------------------------------------------------------
extern "C" void kernel_launch(void* const* d_in, const int* in_sizes, int n_in,
                              void* d_out, int out_size)
{
    (void)in_sizes; (void)n_in; (void)out_size;
    const float* hidden  = (const float*)d_in[0];
    // d_in[1] = ltor_mask (causal tril) — structure exploited directly
    const float* w_qkv   = (const float*)d_in[2];
    const float* b_qkv   = (const float*)d_in[3];
    const float* w_dense = (const float*)d_in[4];
    const float* b_dense = (const float*)d_in[5];
    float* out = (float*)d_out;

    const int GEMM_SMEM  = 98304;    // 3 stages x 32KB
    const int FLASH_SMEM = 196608 + 4096;
    cudaFuncSetAttribute(gemm_mma<0>, cudaFuncAttributeMaxDynamicSharedMemorySize, GEMM_SMEM);
    cudaFuncSetAttribute(gemm_mma<1>, cudaFuncAttributeMaxDynamicSharedMemorySize, GEMM_SMEM);
    cudaFuncSetAttribute(flash_mma,   cudaFuncAttributeMaxDynamicSharedMemorySize, FLASH_SMEM);

    // 0) tf32-round inputs (makes cp.async numerically == cvt.rna path)
    float* d_hid; cudaGetSymbolAddress((void**)&d_hid, g_hid);
    float* d_wq;  cudaGetSymbolAddress((void**)&d_wq,  g_wq);
    float* d_wd;  cudaGetSymbolAddress((void**)&d_wd,  g_wd);
    round4<<<(2 * 2048 * 2048 / 4 + 255) / 256, 256>>>(hidden,  d_hid, 2 * 2048 * 2048 / 4);
    round4<<<(3 * 2048 * 2048 / 4 + 255) / 256, 256>>>(w_qkv,   d_wq,  3 * 2048 * 2048 / 4);
    round4<<<(2048 * 2048 / 4     + 255) / 256, 256>>>(w_dense, d_wd,  2048 * 2048 / 4);

    // 1) QKV: [4096,2048] @ [6144,2048]^T, tiles 128x128
    gemm_mma<0><<<dim3(48, 32), 256, GEMM_SMEM>>>(d_hid, d_wq, b_qkv, nullptr);

    // 2) Causal flash attention (tensor-core) over 32 (b,head) pairs x 16 q-blocks
    flash_mma<<<dim3(16, 32), 256, FLASH_SMEM>>>();

    // 3) Dense: [4096,2048] @ [2048,2048]^T
    gemm_mma<1><<<dim3(16, 32), 256, GEMM_SMEM>>>(nullptr, d_wd, b_dense, out);
}

// round 17
// speedup vs baseline: 2.9082x; 1.0311x over previous
#include <cuda_runtime.h>
#include <cstdint>
#include <cstddef>

// Problem constants (B=2, S=2048, H=2048, N=16 heads, HN=128)
#define S_LEN 2048
#define H_DIM 2048
#define NHEAD 16
#define HDIM  128
static __device__ __constant__ float kRSqrtHD = 0.08838834764831845f; // 1/sqrt(128)

// Scratch (device globals — allowed; no runtime allocation)
__device__ float g_q  [32u * 2048u * 128u];   // [b*16+n][s][d]  tf32-rounded, pre-scaled
__device__ float g_k  [32u * 2048u * 128u];   // [b*16+n][s][d]  tf32-rounded
__device__ float g_vT [32u * 128u * 2048u];   // [b*16+n][d][s]  tf32-rounded
__device__ float g_ctx[2u * 2048u * 2048u];   // [b][s][h]       tf32-rounded
__device__ float g_hid[2u * 2048u * 2048u];   // tf32-rounded hidden
__device__ float g_wq [3u * 2048u * 2048u];   // tf32-rounded w_qkv
__device__ float g_wd [2048u * 2048u];        // tf32-rounded w_dense

// ---------------------------------------------------------------------------
// Helpers (arch-neutral mma.sync/ldmatrix/cp.async; no tcgen05 on sm_103)
// ---------------------------------------------------------------------------
__device__ __forceinline__ uint32_t smem_u32(const void* p) {
    uint32_t a;
    asm("{ .reg .u64 t; cvta.to.shared.u64 t, %1; cvt.u32.u64 %0, t; }"
        : "=r"(a) : "l"(p));
    return a;
}
__device__ __forceinline__ uint32_t f2tf32(float f) {
    uint32_t u;
    asm("cvt.rna.tf32.f32 %0, %1;" : "=r"(u) : "f"(f));
    return u;
}
__device__ __forceinline__ float rtf(float f) { return __uint_as_float(f2tf32(f)); }
#define SWZ(o) ((o) ^ (((o) >> 3) & 0x70))

__device__ __forceinline__ void cp16(uint32_t dst, const void* src) {
    asm volatile("cp.async.cg.shared.global [%0], [%1], 16;"
                 :: "r"(dst), "l"(src) : "memory");
}
#define CP_COMMIT() asm volatile("cp.async.commit_group;" ::: "memory")
#define CP_WAIT(n)  asm volatile("cp.async.wait_group %0;" :: "n"(n) : "memory")

__device__ __forceinline__ void sts_tf32x2(uint32_t addr, float a, float b) {
    uint32_t x = f2tf32(a), y = f2tf32(b);
    asm volatile("st.shared.v2.b32 [%0], {%1, %2};"
                 :: "r"(addr), "r"(x), "r"(y) : "memory");
}

__device__ __forceinline__ void ldsm_x4(uint32_t* r, uint32_t addr) {
    asm volatile("ldmatrix.sync.aligned.m8n8.x4.shared.b16 {%0,%1,%2,%3}, [%4];"
                 : "=r"(r[0]), "=r"(r[1]), "=r"(r[2]), "=r"(r[3])
                 : "r"(addr));
}

__device__ __forceinline__ void mma_tf32(float* c, const uint32_t* a, const uint32_t* b) {
    asm volatile(
        "mma.sync.aligned.m16n8k8.row.col.f32.tf32.tf32.f32 "
        "{%0,%1,%2,%3}, {%4,%5,%6,%7}, {%8,%9}, {%0,%1,%2,%3};"
        : "+f"(c[0]), "+f"(c[1]), "+f"(c[2]), "+f"(c[3])
        : "r"(a[0]), "r"(a[1]), "r"(a[2]), "r"(a[3]),
          "r"(b[0]), "r"(b[1]));
}

// ---------------------------------------------------------------------------
// Pre-pass: tf32-round fp32 arrays in gmem (values become exactly tf32-
// representable, so cp.async raw copies are numerically identical to cvt.rna)
// ---------------------------------------------------------------------------
__global__ void round4(const float* __restrict__ src, float* __restrict__ dst, int n4)
{
    int i = blockIdx.x * blockDim.x + threadIdx.x;
    if (i < n4) {
        float4 v = ((const float4*)src)[i];
        v.x = rtf(v.x); v.y = rtf(v.y); v.z = rtf(v.z); v.w = rtf(v.w);
        ((float4*)dst)[i] = v;
    }
}

// ---------------------------------------------------------------------------
// tf32 mma.sync GEMM with 3-stage cp.async pipeline (ONE barrier per chunk;
// copies for chunk c+2 issued before compute of chunk c).
// C[M,*] = A[M,2048] @ W[Ncols,2048]^T + bias. CTA 128x128, K-chunk 32,
// 8 warps (2x4), warp tile 64x32, fp32 register accumulators, 2 CTAs/SM.
// Inputs MUST be pre-rounded to tf32.
// MODE 0: QKV epilogue (q,k row-major into g_q/g_k; v transposed into g_vT)
// MODE 1: dense epilogue (A is g_ctx; row-major fp32 store to Out)
// ---------------------------------------------------------------------------
template <int MODE>
__global__ void __launch_bounds__(256, 2) gemm_mma(
    const float* __restrict__ Ain,
    const float* __restrict__ W,
    const float* __restrict__ bias,
    float* __restrict__ Out)
{
    constexpr int K = 2048, CK = 32, NC = K / CK, ST = 3;
    extern __shared__ char dynsm[];
    const uint32_t sbase = smem_u32(dynsm);
    // stage s: A @ s*32768, B @ s*32768+16384

    const int tid  = threadIdx.x;
    const int lane = tid & 31;
    const int wid  = tid >> 5;
    const int wm   = wid >> 2;   // 0..1
    const int wn   = wid & 3;    // 0..3
    const int rowBase = blockIdx.y * 128;
    const int colBase = blockIdx.x * 128;
    const float* Aeff = (MODE == 1) ? (const float*)g_ctx : Ain;

    // loader mapping: 2 threads per row, 16 floats (4 x cp.async16) each
    const int lrow = tid >> 1;
    const int lcol = (tid & 1) * 16;
    const float* aP = Aeff + (size_t)(rowBase + lrow) * K + lcol;
    const float* bP = W    + (size_t)(colBase + lrow) * K + lcol;
    uint32_t stoff[4];
#pragma unroll
    for (int g = 0; g < 4; g++)
        stoff[g] = SWZ((uint32_t)lrow * 128u + (uint32_t)(lcol + 4 * g) * 4u);

    // compute-lane ldmatrix constants
    const int xorv  = lane & 7;
    const int aRow  = ((lane >> 3) & 1) * 8 + (lane & 7);
    const int aGoff = lane >> 4;
    const int bRow  = (lane >> 4) * 8 + (lane & 7);
    const int bGoff = (lane >> 3) & 1;

    float acc[4][4][4];
#pragma unroll
    for (int mt = 0; mt < 4; mt++)
#pragma unroll
        for (int nt = 0; nt < 4; nt++)
#pragma unroll
            for (int e = 0; e < 4; e++) acc[mt][nt][e] = 0.0f;

    // ---- cp.async issue for chunk c into stage c%ST ----
    auto issue = [&](int c) {
        const uint32_t Ab = sbase + (uint32_t)(c % ST) * 32768u;
        const float* ap = aP + (size_t)c * CK;
        const float* bp = bP + (size_t)c * CK;
#pragma unroll
        for (int g = 0; g < 4; g++) {
            cp16(Ab + stoff[g], ap + 4 * g);
            cp16(Ab + 16384u + stoff[g], bp + 4 * g);
        }
    };

    issue(0); CP_COMMIT();
    issue(1); CP_COMMIT();

    for (int c = 0; c < NC; c++) {
        CP_WAIT(1);          // chunk c complete (chunk c+1 may be in flight)
        __syncthreads();     // all warps done with stage (c-1)%ST -> reusable

        if (c + 2 < NC) issue(c + 2);   // writes stage (c-1)%ST, safe after sync
        CP_COMMIT();         // one commit per iteration keeps wait(1) exact

        const uint32_t Ab = sbase + (uint32_t)(c % ST) * 32768u;
        const uint32_t aBase = Ab + (uint32_t)(wm * 64 + aRow) * 128u;
        const uint32_t bBase = Ab + 16384u + (uint32_t)(wn * 32 + bRow) * 128u;
#pragma unroll
        for (int ks = 0; ks < 4; ks++) {
            uint32_t afr[4][4], bfr[2][4];
            const uint32_t gA = (uint32_t)(((ks * 2 + aGoff) ^ xorv) * 16);
            const uint32_t gB = (uint32_t)(((ks * 2 + bGoff) ^ xorv) * 16);
#pragma unroll
            for (int mt = 0; mt < 4; mt++)
                ldsm_x4(afr[mt], aBase + (uint32_t)mt * 2048u + gA);
#pragma unroll
            for (int np = 0; np < 2; np++)
                ldsm_x4(bfr[np], bBase + (uint32_t)np * 2048u + gB);
#pragma unroll
            for (int mt = 0; mt < 4; mt++)
#pragma unroll
                for (int nt = 0; nt < 4; nt++)
                    mma_tf32(acc[mt][nt], afr[mt], &bfr[nt >> 1][(nt & 1) * 2]);
        }
    }

    // ---------------- epilogue ----------------
    const int part = colBase >> 11;            // MODE 0: 0=q 1=k 2=v
    const int head = (colBase & 2047) >> 7;
    const int b    = rowBase >> 11;

#pragma unroll
    for (int mt = 0; mt < 4; mt++) {
        const int r_lo = rowBase + wm * 64 + mt * 16 + (lane >> 2);
#pragma unroll
        for (int nt = 0; nt < 4; nt++) {
            const int j = colBase + wn * 32 + nt * 8 + 2 * (lane & 3);
            const float bj0 = bias[j], bj1 = bias[j + 1];
            float v00 = acc[mt][nt][0] + bj0;
            float v01 = acc[mt][nt][1] + bj1;
            float v10 = acc[mt][nt][2] + bj0;
            float v11 = acc[mt][nt][3] + bj1;

            if (MODE == 1) {
                float2 lo = {v00, v01}, hi = {v10, v11};
                *(float2*)&Out[(size_t)r_lo * H_DIM + j]       = lo;
                *(float2*)&Out[(size_t)(r_lo + 8) * H_DIM + j] = hi;
            } else {
                const int s = r_lo & 2047;
                const int d = j & 127;
                if (part < 2) {
                    // q,k: row-major [s][d], tf32-rounded (flash cp.asyncs these)
                    const float sc = part ? 1.0f : kRSqrtHD;
                    float* dst = (part ? g_k : g_q)
                               + ((size_t)(b * NHEAD + head) * S_LEN) * HDIM;
                    float2 lo = {rtf(v00 * sc), rtf(v01 * sc)};
                    float2 hi = {rtf(v10 * sc), rtf(v11 * sc)};
                    *(float2*)&dst[(size_t)s * HDIM + d]       = lo;
                    *(float2*)&dst[(size_t)(s + 8) * HDIM + d] = hi;
                } else {
                    // v: transposed [d][s], tf32-rounded
                    float* dst = g_vT + ((size_t)(b * NHEAD + head) * HDIM) * (size_t)S_LEN;
                    dst[(size_t)d       * S_LEN + s]     = rtf(v00);
                    dst[(size_t)(d + 1) * S_LEN + s]     = rtf(v01);
                    dst[(size_t)d       * S_LEN + s + 8] = rtf(v10);
                    dst[(size_t)(d + 1) * S_LEN + s + 8] = rtf(v11);
                }
            }
        }
    }
}

// ---------------------------------------------------------------------------
// Causal flash attention with tf32 mma.sync; Q/K/V via cp.async (pre-rounded).
// K and V are separate commit groups: S=QK^T starts as soon as K lands,
// the V copy drains behind S-MMA + softmax (wait before the P-store barrier).
// CTA: 128 q-rows, tiles of 128 k-cols. 8 warps (2x4), warp 64x32.
// Smem: Qs 64KB | K-tile (reused as P) 64KB | V 64KB | stats 4KB
// ---------------------------------------------------------------------------
__global__ void __launch_bounds__(256) flash_mma()
{
    extern __shared__ char dynsm[];
    const uint32_t QsB  = smem_u32(dynsm);
    const uint32_t KPsB = QsB + 65536u;
    const uint32_t VsB  = QsB + 131072u;
    float* pmax = (float*)(dynsm + 196608);          // [128][4]
    float* psum = (float*)(dynsm + 196608 + 2048);   // [128][4]

    const int tid  = threadIdx.x;
    const int lane = tid & 31;
    const int wid  = tid >> 5;
    const int wm   = wid >> 2;
    const int wn   = wid & 3;
    const int qb   = (int)(gridDim.x - 1) - (int)blockIdx.x;  // longest first
    const int bh   = blockIdx.y;

    const int xorv  = lane & 7;
    const int aRow  = ((lane >> 3) & 1) * 8 + (lane & 7);
    const int aGoff = lane >> 4;
    const int bRow  = (lane >> 4) * 8 + (lane & 7);
    const int bGoff = (lane >> 3) & 1;

    const int lrow = tid >> 1;
    const int lcol = (tid & 1) * 16;
    uint32_t stoff[4];
#pragma unroll
    for (int g = 0; g < 4; g++)
        stoff[g] = SWZ((uint32_t)lrow * 128u + (uint32_t)(lcol + 4 * g) * 4u);

    const float* gq = g_q  + (size_t)bh * S_LEN * HDIM + (size_t)qb * 128 * HDIM;
    const float* gk = g_k  + (size_t)bh * S_LEN * HDIM;
    const float* gv = g_vT + (size_t)bh * HDIM * S_LEN;

    // ---- Q tile via cp.async ----
#pragma unroll
    for (int ksub = 0; ksub < 4; ksub++)
#pragma unroll
        for (int g = 0; g < 4; g++)
            cp16(QsB + (uint32_t)ksub * 16384u + stoff[g],
                 &gq[(size_t)lrow * HDIM + ksub * 32 + lcol + 4 * g]);
    CP_COMMIT();

    float o[4][4][4];
    float Mr[8], Lr[8];
#pragma unroll
    for (int i = 0; i < 8; i++) { Mr[i] = -1e30f; Lr[i] = 0.0f; }
#pragma unroll
    for (int mt = 0; mt < 4; mt++)
#pragma unroll
        for (int nt = 0; nt < 4; nt++)
#pragma unroll
            for (int e = 0; e < 4; e++) o[mt][nt][e] = 0.0f;

    for (int kb = 0; kb <= qb; kb++) {
        // ---- K group, then V group (V drains behind S-MMA + softmax) ----
        const float* gkt = gk + (size_t)kb * 128 * HDIM;
        const float* gvt = gv + (size_t)kb * 128;
#pragma unroll
        for (int ksub = 0; ksub < 4; ksub++)
#pragma unroll
            for (int g = 0; g < 4; g++)
                cp16(KPsB + (uint32_t)ksub * 16384u + stoff[g],
                     &gkt[(size_t)lrow * HDIM + ksub * 32 + lcol + 4 * g]);
        CP_COMMIT();
#pragma unroll
        for (int ksub = 0; ksub < 4; ksub++)
#pragma unroll
            for (int g = 0; g < 4; g++)
                cp16(VsB + (uint32_t)ksub * 16384u + stoff[g],
                     &gvt[(size_t)lrow * S_LEN + ksub * 32 + lcol + 4 * g]);
        CP_COMMIT();
        CP_WAIT(1);          // K (and Q on first iter) ready; V in flight
        __syncthreads();

        // ---- S = Q K^T ----
        float sAcc[4][4][4];
#pragma unroll
        for (int mt = 0; mt < 4; mt++)
#pragma unroll
            for (int nt = 0; nt < 4; nt++)
#pragma unroll
                for (int e = 0; e < 4; e++) sAcc[mt][nt][e] = 0.0f;

#pragma unroll
        for (int ks = 0; ks < 16; ks++) {
            const int ksub = ks >> 2, k2 = ks & 3;
            uint32_t afr[4][4], bfr[2][4];
            const uint32_t gA = (uint32_t)(((k2 * 2 + aGoff) ^ xorv) * 16);
            const uint32_t gB = (uint32_t)(((k2 * 2 + bGoff) ^ xorv) * 16);
            const uint32_t aB = QsB  + (uint32_t)ksub * 16384u + (uint32_t)(wm * 64 + aRow) * 128u;
            const uint32_t bB = KPsB + (uint32_t)ksub * 16384u + (uint32_t)(wn * 32 + bRow) * 128u;
#pragma unroll
            for (int mt = 0; mt < 4; mt++)
                ldsm_x4(afr[mt], aB + (uint32_t)mt * 2048u + gA);
#pragma unroll
            for (int np = 0; np < 2; np++)
                ldsm_x4(bfr[np], bB + (uint32_t)np * 2048u + gB);
#pragma unroll
            for (int mt = 0; mt < 4; mt++)
#pragma unroll
                for (int nt = 0; nt < 4; nt++)
                    mma_tf32(sAcc[mt][nt], afr[mt], &bfr[nt >> 1][(nt & 1) * 2]);
        }

        // ---- causal mask on diagonal tile ----
        if (kb == qb) {
#pragma unroll
            for (int mt = 0; mt < 4; mt++)
#pragma unroll
                for (int h = 0; h < 2; h++) {
                    const int lr = wm * 64 + mt * 16 + (lane >> 2) + h * 8;
#pragma unroll
                    for (int nt = 0; nt < 4; nt++) {
                        const int lc = wn * 32 + nt * 8 + 2 * (lane & 3);
                        if (lc     > lr) sAcc[mt][nt][h * 2 + 0] = -1e30f;
                        if (lc + 1 > lr) sAcc[mt][nt][h * 2 + 1] = -1e30f;
                    }
                }
        }

        // ---- stats pass 1: warp-partial row max -> smem ----
#pragma unroll
        for (int mt = 0; mt < 4; mt++)
#pragma unroll
            for (int h = 0; h < 2; h++) {
                float m = -1e30f;
#pragma unroll
                for (int nt = 0; nt < 4; nt++)
                    m = fmaxf(m, fmaxf(sAcc[mt][nt][h * 2], sAcc[mt][nt][h * 2 + 1]));
                m = fmaxf(m, __shfl_xor_sync(0xffffffffu, m, 1));
                m = fmaxf(m, __shfl_xor_sync(0xffffffffu, m, 2));
                if ((lane & 3) == 0)
                    pmax[(wm * 64 + mt * 16 + (lane >> 2) + h * 8) * 4 + wn] = m;
            }
        __syncthreads();   // all S-mma ldsm done -> K buffer reusable as P

        // ---- stats pass 2: exp, partial sums, rescale O, store P ----
#pragma unroll
        for (int mt = 0; mt < 4; mt++)
#pragma unroll
            for (int h = 0; h < 2; h++) {
                const int idx = mt * 2 + h;
                const int row = wm * 64 + mt * 16 + (lane >> 2) + h * 8;
                float4 pm = *(float4*)&pmax[row * 4];
                float mnew = fmaxf(fmaxf(pm.x, pm.y), fmaxf(pm.z, pm.w));
                mnew = fmaxf(mnew, Mr[idx]);
                const float corr = __expf(Mr[idx] - mnew);
                Mr[idx] = mnew;
                float rs = 0.0f;
#pragma unroll
                for (int nt = 0; nt < 4; nt++) {
                    float p0 = __expf(sAcc[mt][nt][h * 2]     - mnew);
                    float p1 = __expf(sAcc[mt][nt][h * 2 + 1] - mnew);
                    sAcc[mt][nt][h * 2]     = p0;
                    sAcc[mt][nt][h * 2 + 1] = p1;
                    rs += p0 + p1;
                }
                rs += __shfl_xor_sync(0xffffffffu, rs, 1);
                rs += __shfl_xor_sync(0xffffffffu, rs, 2);
                if ((lane & 3) == 0) psum[row * 4 + wn] = rs;
                Lr[idx] *= corr;
#pragma unroll
                for (int nt = 0; nt < 4; nt++) {
                    o[mt][nt][h * 2]     *= corr;
                    o[mt][nt][h * 2 + 1] *= corr;
                }
#pragma unroll
                for (int nt = 0; nt < 4; nt++) {
                    const uint32_t col4 = (uint32_t)(nt * 8 + 2 * (lane & 3)) * 4u;
                    const uint32_t addr = KPsB + (uint32_t)wn * 16384u
                                        + SWZ((uint32_t)row * 128u + col4);
                    sts_tf32x2(addr, sAcc[mt][nt][h * 2], sAcc[mt][nt][h * 2 + 1]);
                }
            }
        CP_WAIT(0);        // V landed (visibility across threads via next barrier)
        __syncthreads();

        // ---- Lr += global row sum ----
#pragma unroll
        for (int mt = 0; mt < 4; mt++)
#pragma unroll
            for (int h = 0; h < 2; h++) {
                const int row = wm * 64 + mt * 16 + (lane >> 2) + h * 8;
                float4 ps = *(float4*)&psum[row * 4];
                Lr[mt * 2 + h] += (ps.x + ps.y) + (ps.z + ps.w);
            }

        // ---- O += P V ----
#pragma unroll
        for (int ks = 0; ks < 16; ks++) {
            const int ksub = ks >> 2, k2 = ks & 3;
            uint32_t afr[4][4], bfr[2][4];
            const uint32_t gA = (uint32_t)(((k2 * 2 + aGoff) ^ xorv) * 16);
            const uint32_t gB = (uint32_t)(((k2 * 2 + bGoff) ^ xorv) * 16);
            const uint32_t aB = KPsB + (uint32_t)ksub * 16384u + (uint32_t)(wm * 64 + aRow) * 128u;
            const uint32_t bB = VsB  + (uint32_t)ksub * 16384u + (uint32_t)(wn * 32 + bRow) * 128u;
#pragma unroll
            for (int mt = 0; mt < 4; mt++)
                ldsm_x4(afr[mt], aB + (uint32_t)mt * 2048u + gA);
#pragma unroll
            for (int np = 0; np < 2; np++)
                ldsm_x4(bfr[np], bB + (uint32_t)np * 2048u + gB);
#pragma unroll
            for (int mt = 0; mt < 4; mt++)
#pragma unroll
                for (int nt = 0; nt < 4; nt++)
                    mma_tf32(o[mt][nt], afr[mt], &bfr[nt >> 1][(nt & 1) * 2]);
        }
        __syncthreads();   // P/V buffers free for next kb
    }

    // ---- normalize and store ctx [b][s][h] (tf32-rounded for dense cp.async) ----
    const int b = bh >> 4;
    const int n = bh & 15;
#pragma unroll
    for (int mt = 0; mt < 4; mt++)
#pragma unroll
        for (int h = 0; h < 2; h++) {
            const int row = qb * 128 + wm * 64 + mt * 16 + (lane >> 2) + h * 8;
            const float inv = 1.0f / Lr[mt * 2 + h];
            float* dst = g_ctx + ((size_t)b * S_LEN + row) * H_DIM + n * HDIM;
#pragma unroll
            for (int nt = 0; nt < 4; nt++) {
                const int col = wn * 32 + nt * 8 + 2 * (lane & 3);
                float2 v = {rtf(o[mt][nt][h * 2] * inv), rtf(o[mt][nt][h * 2 + 1] * inv)};
                *(float2*)&dst[col] = v;
            }
        }
}

// ---------------------------------------------------------------------------
extern "C" void kernel_launch(void* const* d_in, const int* in_sizes, int n_in,
                              void* d_out, int out_size)
{
    (void)in_sizes; (void)n_in; (void)out_size;
    const float* hidden  = (const float*)d_in[0];
    // d_in[1] = ltor_mask (causal tril) — structure exploited directly
    const float* w_qkv   = (const float*)d_in[2];
    const float* b_qkv   = (const float*)d_in[3];
    const float* w_dense = (const float*)d_in[4];
    const float* b_dense = (const float*)d_in[5];
    float* out = (float*)d_out;

    const int GEMM_SMEM  = 98304;    // 3 stages x 32KB
    const int FLASH_SMEM = 196608 + 4096;
    cudaFuncSetAttribute(gemm_mma<0>, cudaFuncAttributeMaxDynamicSharedMemorySize, GEMM_SMEM);
    cudaFuncSetAttribute(gemm_mma<1>, cudaFuncAttributeMaxDynamicSharedMemorySize, GEMM_SMEM);
    cudaFuncSetAttribute(flash_mma,   cudaFuncAttributeMaxDynamicSharedMemorySize, FLASH_SMEM);

    // 0) tf32-round inputs (makes cp.async numerically == cvt.rna path)
    float* d_hid; cudaGetSymbolAddress((void**)&d_hid, g_hid);
    float* d_wq;  cudaGetSymbolAddress((void**)&d_wq,  g_wq);
    float* d_wd;  cudaGetSymbolAddress((void**)&d_wd,  g_wd);
    round4<<<(2 * 2048 * 2048 / 4 + 255) / 256, 256>>>(hidden,  d_hid, 2 * 2048 * 2048 / 4);
    round4<<<(3 * 2048 * 2048 / 4 + 255) / 256, 256>>>(w_qkv,   d_wq,  3 * 2048 * 2048 / 4);
    round4<<<(2048 * 2048 / 4     + 255) / 256, 256>>>(w_dense, d_wd,  2048 * 2048 / 4);

    // 1) QKV: [4096,2048] @ [6144,2048]^T, tiles 128x128
    gemm_mma<0><<<dim3(48, 32), 256, GEMM_SMEM>>>(d_hid, d_wq, b_qkv, nullptr);

    // 2) Causal flash attention (tensor-core) over 32 (b,head) pairs x 16 q-blocks
    flash_mma<<<dim3(16, 32), 256, FLASH_SMEM>>>();

    // 3) Dense: [4096,2048] @ [2048,2048]^T
    gemm_mma<1><<<dim3(16, 32), 256, GEMM_SMEM>>>(nullptr, d_wd, b_dense, out);
}